// round 5
// baseline (speedup 1.0000x reference)
#include <cuda_runtime.h>
#include <math.h>

// ---------------- problem constants ----------------
#define BB   4
#define SS   4096
#define DD   1280
#define SKV  77
#define CDIM 2048
#define NH   20
#define HDIM 64
#define MQ   (BB*SS)    // 16384
#define MKV  (BB*SKV)   // 308

// ---------------- scratch ----------------
__device__ float g_Q   [MQ  * DD];   // 84 MB
__device__ float g_K   [MKV * DD];
__device__ float g_V   [MKV * DD];
__device__ float g_Kip [MKV * DD];
__device__ float g_Vip [MKV * DD];
__device__ float g_comb[MQ  * DD];   // 84 MB
__device__ float g_boost;

// ============================================================
// Double-buffered 128x128 SGEMM, KT=8, 256 threads, 8x8 microtile
// C[M,N] = A[M,K] @ B[K,N] (+ bias).  N, K multiples of 8/128 as used.
// ============================================================
template<bool CHECK_M, bool BIAS>
__global__ __launch_bounds__(256, 2)
void sgemm_kernel(const float* __restrict__ A, const float* __restrict__ Bm,
                  const float* __restrict__ bias, float* __restrict__ C,
                  int M, int N, int K)
{
    __shared__ float As[2][8][128];
    __shared__ float Bs[2][8][128];

    const int tid = threadIdx.x;
    const int tx  = tid & 15;
    const int ty  = tid >> 4;
    const int r0  = ty << 3;
    const int c0  = tx << 3;
    const int bm  = blockIdx.x * 128;
    const int bn  = blockIdx.y * 128;

    const int arow = tid >> 1;          // 0..127
    const int acol = (tid & 1) << 2;    // 0 or 4
    const int brow = tid >> 5;          // 0..7
    const int bcol = (tid & 31) << 2;   // 0..124

    float acc[8][8];
#pragma unroll
    for (int i = 0; i < 8; ++i)
#pragma unroll
        for (int j = 0; j < 8; ++j) acc[i][j] = 0.f;

    // prologue: stage kt=0 into buf 0
    {
        const int row = bm + arow;
        float4 av = make_float4(0.f, 0.f, 0.f, 0.f);
        if (!CHECK_M || row < M)
            av = *(const float4*)(A + (size_t)row * K + acol);
        As[0][acol + 0][arow] = av.x;
        As[0][acol + 1][arow] = av.y;
        As[0][acol + 2][arow] = av.z;
        As[0][acol + 3][arow] = av.w;
        float4 bv = *(const float4*)(Bm + (size_t)brow * N + bn + bcol);
        *(float4*)&Bs[0][brow][bcol] = bv;
    }
    __syncthreads();

    for (int kt = 0; kt < K; kt += 8) {
        const int  buf  = (kt >> 3) & 1;
        const bool more = (kt + 8) < K;
        float4 a_reg = make_float4(0.f, 0.f, 0.f, 0.f);
        float4 b_reg = make_float4(0.f, 0.f, 0.f, 0.f);
        if (more) {
            const int row = bm + arow;
            if (!CHECK_M || row < M)
                a_reg = *(const float4*)(A + (size_t)row * K + (kt + 8) + acol);
            b_reg = *(const float4*)(Bm + (size_t)(kt + 8 + brow) * N + bn + bcol);
        }
#pragma unroll
        for (int kk = 0; kk < 8; ++kk) {
            float4 a0 = *(const float4*)&As[buf][kk][r0];
            float4 a1 = *(const float4*)&As[buf][kk][r0 + 4];
            float4 b0 = *(const float4*)&Bs[buf][kk][c0];
            float4 b1 = *(const float4*)&Bs[buf][kk][c0 + 4];
            float ar[8] = {a0.x, a0.y, a0.z, a0.w, a1.x, a1.y, a1.z, a1.w};
            float br[8] = {b0.x, b0.y, b0.z, b0.w, b1.x, b1.y, b1.z, b1.w};
#pragma unroll
            for (int i = 0; i < 8; ++i)
#pragma unroll
                for (int j = 0; j < 8; ++j)
                    acc[i][j] = fmaf(ar[i], br[j], acc[i][j]);
        }
        if (more) {
            const int nb = buf ^ 1;
            As[nb][acol + 0][arow] = a_reg.x;
            As[nb][acol + 1][arow] = a_reg.y;
            As[nb][acol + 2][arow] = a_reg.z;
            As[nb][acol + 3][arow] = a_reg.w;
            *(float4*)&Bs[nb][brow][bcol] = b_reg;
            __syncthreads();
        }
    }

    // epilogue
    float bi[8];
    if (BIAS) {
#pragma unroll
        for (int j = 0; j < 8; ++j) bi[j] = bias[bn + c0 + j];
    }
#pragma unroll
    for (int i = 0; i < 8; ++i) {
        const int row = bm + r0 + i;
        if (CHECK_M && row >= M) continue;
        float4 o0, o1;
        o0.x = acc[i][0]; o0.y = acc[i][1]; o0.z = acc[i][2]; o0.w = acc[i][3];
        o1.x = acc[i][4]; o1.y = acc[i][5]; o1.z = acc[i][6]; o1.w = acc[i][7];
        if (BIAS) {
            o0.x += bi[0]; o0.y += bi[1]; o0.z += bi[2]; o0.w += bi[3];
            o1.x += bi[4]; o1.y += bi[5]; o1.z += bi[6]; o1.w += bi[7];
        }
        *(float4*)(C + (size_t)row * N + bn + c0)     = o0;
        *(float4*)(C + (size_t)row * N + bn + c0 + 4) = o1;
    }
}

// ============================================================
// Boost: ratio = mean(mask); boost per reference formula
// ============================================================
__global__ void boost_kernel(const float* __restrict__ mask)
{
    __shared__ float red[128];
    float s = 0.f;
    for (int i = threadIdx.x; i < SS; i += 128) s += mask[i];
    red[threadIdx.x] = s;
    __syncthreads();
    for (int o = 64; o > 0; o >>= 1) {
        if (threadIdx.x < o) red[threadIdx.x] += red[threadIdx.x + o];
        __syncthreads();
    }
    if (threadIdx.x == 0) {
        float ratio = red[0] * (1.0f / (float)SS);
        float b = 1.0f;
        if (ratio > 1e-6f && ratio < 0.1f)
            b = fminf(1.0f + (0.1f - ratio) * 30.0f, 4.0f);
        g_boost = b;
    }
}

// ============================================================
// Fused dual-branch attention for one (b,h) x 128 query rows.
// comb = attn(Q,K,V) + mask*boost*attn(Q,Kip,Vip)
// ============================================================
#define QSTR 68
#define KSTR 84
#define PSTR 80
#define ATT_SMEM_FLOATS (128*QSTR + 64*KSTR + 128*PSTR + 80*64)
#define ATT_SMEM_BYTES  (ATT_SMEM_FLOATS * 4)

__global__ __launch_bounds__(256, 1)
void attn_kernel(const float* __restrict__ msk)
{
    extern __shared__ float sm[];
    float* Qs = sm;                    // [128][QSTR]
    float* Ks = Qs + 128 * QSTR;       // [64][KSTR]  (transposed, keys padded to 80)
    float* Ps = Ks + 64 * KSTR;        // [128][PSTR]
    float* Vs = Ps + 128 * PSTR;       // [80][64]

    const int tid = threadIdx.x;
    const int tx  = tid & 15;
    const int ty  = tid >> 4;
    const int r0  = ty << 3;                 // 8 rows per thread
    const int t0  = tx << 2;                 // 4 keys + key (64+tx)
    const int c0  = tx << 2;                 // 4 output dims
    const int b   = blockIdx.y / NH;
    const int h   = blockIdx.y % NH;
    const int s0  = blockIdx.x * 128;

    // ---- load Q tile [128][64] ----
    {
        const float* qb = g_Q + (size_t)(b * SS + s0) * DD + h * HDIM;
#pragma unroll
        for (int k = 0; k < 8; ++k) {
            int fidx = tid + k * 256;          // 2048 float4s
            int r  = fidx >> 4;
            int d4 = (fidx & 15) << 2;
            float4 v = *(const float4*)(qb + (size_t)r * DD + d4);
            *(float4*)(Qs + r * QSTR + d4) = v;
        }
    }

    float o1[8][4];

    for (int br = 0; br < 2; ++br) {
        const float* kb = (br ? g_Kip : g_K) + (size_t)(b * SKV) * DD + h * HDIM;
        const float* vb = (br ? g_Vip : g_V) + (size_t)(b * SKV) * DD + h * HDIM;

        // K transposed into smem: Ks[d][t]
        for (int idx = tid; idx < 80 * 64; idx += 256) {
            int t = idx >> 6, d = idx & 63;
            Ks[d * KSTR + t] = (t < SKV) ? kb[(size_t)t * DD + d] : 0.f;
        }
        __syncthreads();   // Q+K ready; also fences prev-branch P/V readers

        // ---- scores: S[r][t] = q . k ----
        float acc[8][5];
#pragma unroll
        for (int i = 0; i < 8; ++i)
#pragma unroll
            for (int j = 0; j < 5; ++j) acc[i][j] = 0.f;

#pragma unroll 2
        for (int d = 0; d < 64; ++d) {
            float4 k4 = *(const float4*)(Ks + d * KSTR + t0);
            float  k5 = Ks[d * KSTR + 64 + tx];
            float kr[5] = {k4.x, k4.y, k4.z, k4.w, k5};
#pragma unroll
            for (int i = 0; i < 8; ++i) {
                float q = Qs[(r0 + i) * QSTR + d];
#pragma unroll
                for (int j = 0; j < 5; ++j)
                    acc[i][j] = fmaf(q, kr[j], acc[i][j]);
            }
        }

        // ---- softmax over 77 keys (16 threads per row share keys) ----
        const bool pad5 = (64 + tx) >= SKV;
#pragma unroll
        for (int i = 0; i < 8; ++i) {
#pragma unroll
            for (int j = 0; j < 5; ++j) acc[i][j] *= 0.125f;
            if (pad5) acc[i][4] = -INFINITY;
            float m = acc[i][0];
#pragma unroll
            for (int j = 1; j < 5; ++j) m = fmaxf(m, acc[i][j]);
#pragma unroll
            for (int o = 1; o < 16; o <<= 1)
                m = fmaxf(m, __shfl_xor_sync(0xffffffffu, m, o));
            float s = 0.f;
#pragma unroll
            for (int j = 0; j < 5; ++j) { acc[i][j] = __expf(acc[i][j] - m); s += acc[i][j]; }
#pragma unroll
            for (int o = 1; o < 16; o <<= 1)
                s += __shfl_xor_sync(0xffffffffu, s, o);
            float inv = 1.0f / s;
            Ps[(r0 + i) * PSTR + t0 + 0] = acc[i][0] * inv;
            Ps[(r0 + i) * PSTR + t0 + 1] = acc[i][1] * inv;
            Ps[(r0 + i) * PSTR + t0 + 2] = acc[i][2] * inv;
            Ps[(r0 + i) * PSTR + t0 + 3] = acc[i][3] * inv;
            Ps[(r0 + i) * PSTR + 64 + tx] = acc[i][4] * inv;
        }

        // V into smem: Vs[t][d]
        for (int idx = tid; idx < 80 * 64; idx += 256) {
            int t = idx >> 6, d = idx & 63;
            Vs[t * 64 + d] = (t < SKV) ? vb[(size_t)t * DD + d] : 0.f;
        }
        __syncthreads();   // P + V ready

        // ---- O = P @ V ----
        float acc2[8][4];
#pragma unroll
        for (int i = 0; i < 8; ++i)
#pragma unroll
            for (int c = 0; c < 4; ++c) acc2[i][c] = 0.f;

        for (int t = 0; t < SKV; ++t) {
            float4 v4 = *(const float4*)(Vs + t * 64 + c0);
#pragma unroll
            for (int i = 0; i < 8; ++i) {
                float p = Ps[(r0 + i) * PSTR + t];
                acc2[i][0] = fmaf(p, v4.x, acc2[i][0]);
                acc2[i][1] = fmaf(p, v4.y, acc2[i][1]);
                acc2[i][2] = fmaf(p, v4.z, acc2[i][2]);
                acc2[i][3] = fmaf(p, v4.w, acc2[i][3]);
            }
        }

        if (br == 0) {
#pragma unroll
            for (int i = 0; i < 8; ++i)
#pragma unroll
                for (int c = 0; c < 4; ++c) o1[i][c] = acc2[i][c];
        } else {
            const float boost = g_boost;
            float* cb = g_comb + (size_t)(b * SS + s0) * DD + h * HDIM;
#pragma unroll
            for (int i = 0; i < 8; ++i) {
                float mb = msk[s0 + r0 + i] * boost;
                float4 o;
                o.x = o1[i][0] + mb * acc2[i][0];
                o.y = o1[i][1] + mb * acc2[i][1];
                o.z = o1[i][2] + mb * acc2[i][2];
                o.w = o1[i][3] + mb * acc2[i][3];
                *(float4*)(cb + (size_t)(r0 + i) * DD + c0) = o;
            }
        }
    }
}

// ============================================================
// launch
// ============================================================
extern "C" void kernel_launch(void* const* d_in, const int* in_sizes, int n_in,
                              void* d_out, int out_size)
{
    const float* hs   = (const float*)d_in[0];
    const float* ehs  = (const float*)d_in[1];
    const float* msk  = (const float*)d_in[2];
    const float* Wq   = (const float*)d_in[3];
    const float* Wk   = (const float*)d_in[4];
    const float* Wv   = (const float*)d_in[5];
    const float* Wkip = (const float*)d_in[6];
    const float* Wvip = (const float*)d_in[7];
    const float* Wo   = (const float*)d_in[8];
    const float* bo   = (const float*)d_in[9];
    float* out = (float*)d_out;

    float *gq, *gk, *gv, *gki, *gvi, *gc;
    cudaGetSymbolAddress((void**)&gq,  g_Q);
    cudaGetSymbolAddress((void**)&gk,  g_K);
    cudaGetSymbolAddress((void**)&gv,  g_V);
    cudaGetSymbolAddress((void**)&gki, g_Kip);
    cudaGetSymbolAddress((void**)&gvi, g_Vip);
    cudaGetSymbolAddress((void**)&gc,  g_comb);

    cudaFuncSetAttribute(attn_kernel,
                         cudaFuncAttributeMaxDynamicSharedMemorySize,
                         ATT_SMEM_BYTES);

    // Q projection: [16384,1280] @ [1280,1280]
    sgemm_kernel<false, false><<<dim3(MQ / 128, DD / 128), 256>>>(
        hs, Wq, nullptr, gq, MQ, DD, DD);

    // K/V/Kip/Vip projections: [308,2048] @ [2048,1280]
    sgemm_kernel<true, false><<<dim3(3, DD / 128), 256>>>(
        ehs, Wk,   nullptr, gk,  MKV, DD, CDIM);
    sgemm_kernel<true, false><<<dim3(3, DD / 128), 256>>>(
        ehs, Wv,   nullptr, gv,  MKV, DD, CDIM);
    sgemm_kernel<true, false><<<dim3(3, DD / 128), 256>>>(
        ehs, Wkip, nullptr, gki, MKV, DD, CDIM);
    sgemm_kernel<true, false><<<dim3(3, DD / 128), 256>>>(
        ehs, Wvip, nullptr, gvi, MKV, DD, CDIM);

    boost_kernel<<<1, 128>>>(msk);

    // fused dual-branch attention -> g_comb
    attn_kernel<<<dim3(SS / 128, BB * NH), 256, ATT_SMEM_BYTES>>>(msk);

    // output projection + bias: [16384,1280] @ [1280,1280] + bo
    sgemm_kernel<false, true><<<dim3(MQ / 128, DD / 128), 256>>>(
        gc, Wo, bo, out, MQ, DD, DD);
}

// round 7
// speedup vs baseline: 2.9303x; 2.9303x over previous
#include <cuda_runtime.h>
#include <cuda_bf16.h>
#include <math.h>
#include <stdint.h>

// ---------------- problem constants ----------------
#define BB   4
#define SS   4096
#define DD   1280
#define SKV  77
#define CDIM 2048
#define NH   20
#define HDIM 64
#define MQ   (BB*SS)    // 16384
#define MKV  (BB*SKV)   // 308
#define KVLD 5120       // fused KV output row stride: [K|V|Kip|Vip]

// ---------------- scratch ----------------
__device__ __nv_bfloat16 g_Asplit[(size_t)MQ * 2 * DD];      // [16384, 2560]  (hi|lo)
__device__ __nv_bfloat16 g_W3    [(size_t)DD * 3 * DD];      // [1280, 3840]
__device__ __nv_bfloat16 g_Wkv3  [(size_t)4 * DD * 3 * CDIM];// [5120, 6144]
__device__ __nv_bfloat16 g_Akv   [(size_t)MKV * 2 * CDIM];   // [308, 4096]
__device__ float g_Q   [(size_t)MQ * DD];
__device__ float g_KV  [(size_t)MKV * KVLD];
__device__ float g_comb[(size_t)MQ * DD];
__device__ float g_boost;

// ---------------- helpers ----------------
__device__ __forceinline__ uint32_t swz128(uint32_t b) { return b ^ ((b >> 3) & 0x70); }

#define CP_COMMIT()  asm volatile("cp.async.commit_group;" ::: "memory")
#define CP_WAIT1()   asm volatile("cp.async.wait_group 1;" ::: "memory")
#define CP_WAIT0()   asm volatile("cp.async.wait_group 0;" ::: "memory")

#define LDSM_X4(r0,r1,r2,r3,addr) \
    asm volatile("ldmatrix.sync.aligned.m8n8.x4.shared.b16 {%0,%1,%2,%3}, [%4];" \
                 : "=r"(r0), "=r"(r1), "=r"(r2), "=r"(r3) : "r"(addr))

#define MMA16816(d, a, b0, b1) \
    asm volatile("mma.sync.aligned.m16n8k16.row.col.f32.bf16.bf16.f32 " \
                 "{%0,%1,%2,%3}, {%4,%5,%6,%7}, {%8,%9}, {%0,%1,%2,%3};" \
                 : "+f"((d)[0]), "+f"((d)[1]), "+f"((d)[2]), "+f"((d)[3]) \
                 : "r"((a)[0]), "r"((a)[1]), "r"((a)[2]), "r"((a)[3]), \
                   "r"(b0), "r"(b1))

// ============================================================
// HMMA bf16 GEMM: CTA 128x128, 4 warps (2x2 of 64x64), K-chunk 64 bf16,
// double-buffered cp.async + ldmatrix, SW128 swizzle.
//   A' layout: [M, 2K] bf16 = [hi | lo], chunk kA(c) = c<wrapA ? c : c-wrapA
//   B' layout: [N, 3K] bf16 = [hi | hi | lo] (K-major, pre-transposed)
// ============================================================
#define SM_A0   0
#define SM_B0   16384
#define SM_A1   32768
#define SM_B1   49152
#define GEMM_SMEM 65536

template<bool CHECK_M>
__device__ __forceinline__ void stage_chunk(uint32_t sb, uint32_t aoff, uint32_t boff,
                                            const char* ab, int ldAb,
                                            const char* bb, int ldBb,
                                            int bm, int M, int tid)
{
#pragma unroll
    for (int i = 0; i < 8; ++i) {
        int idx = tid + i * 128;
        int r = idx >> 3, seg = idx & 7;
        uint32_t d = sb + aoff + swz128((uint32_t)(r * 128 + seg * 16));
        const char* s = ab + (size_t)r * ldAb + seg * 16;
        int sz = (!CHECK_M || (bm + r) < M) ? 16 : 0;
        asm volatile("cp.async.cg.shared.global [%0], [%1], 16, %2;"
                     :: "r"(d), "l"(s), "r"(sz) : "memory");
    }
#pragma unroll
    for (int i = 0; i < 8; ++i) {
        int idx = tid + i * 128;
        int r = idx >> 3, seg = idx & 7;
        uint32_t d = sb + boff + swz128((uint32_t)(r * 128 + seg * 16));
        const char* s = bb + (size_t)r * ldBb + seg * 16;
        asm volatile("cp.async.cg.shared.global [%0], [%1], 16;"
                     :: "r"(d), "l"(s) : "memory");
    }
}

template<bool CHECK_M, bool BIAS>
__global__ __launch_bounds__(128, 2)
void hmma_gemm(const __nv_bfloat16* __restrict__ A, int ldA, int wrapA,
               const __nv_bfloat16* __restrict__ Bw, int ldB, int NC,
               const float* __restrict__ bias,
               float* __restrict__ C, int ldC, int M)
{
    extern __shared__ char smem_raw[];
    const uint32_t sb = (uint32_t)__cvta_generic_to_shared(smem_raw);
    const int tid  = threadIdx.x;
    const int lane = tid & 31;
    const int wid  = tid >> 5;
    const int wm   = wid & 1;        // warp row (m offset wm*64)
    const int wn   = wid >> 1;       // warp col (n offset wn*64)
    const int bm   = blockIdx.x * 128;
    const int bn   = blockIdx.y * 128;

    const int ldAb = ldA * 2;        // byte strides
    const int ldBb = ldB * 2;
    const char* Abase = (const char*)A + (size_t)bm * ldAb;
    const char* Bbase = (const char*)Bw + (size_t)bn * ldBb;

    float acc[4][8][4];
#pragma unroll
    for (int mt = 0; mt < 4; ++mt)
#pragma unroll
        for (int nb = 0; nb < 8; ++nb)
#pragma unroll
            for (int e = 0; e < 4; ++e) acc[mt][nb][e] = 0.f;

    // ldmatrix lane address components
    const int a_row  = (lane & 7) + ((lane & 8) ? 8 : 0);
    const int a_colb = (lane & 16) ? 16 : 0;
    const int b_row  = (lane & 7) + ((lane & 16) ? 8 : 0);
    const int b_colb = (lane & 8) ? 16 : 0;

    // prologue: chunk 0 -> buf 0
    stage_chunk<CHECK_M>(sb, SM_A0, SM_B0, Abase, ldAb, Bbase + 0, ldBb, bm, M, tid);
    CP_COMMIT();

    for (int c = 0; c < NC; ++c) {
        const bool more = (c + 1) < NC;
        if (more) {
            const int cn = c + 1;
            const int kAn = (cn < wrapA) ? cn : cn - wrapA;
            const uint32_t aoff = (cn & 1) ? SM_A1 : SM_A0;
            const uint32_t boff = (cn & 1) ? SM_B1 : SM_B0;
            stage_chunk<CHECK_M>(sb, aoff, boff,
                                 Abase + (size_t)kAn * 128, ldAb,
                                 Bbase + (size_t)cn  * 128, ldBb, bm, M, tid);
            CP_COMMIT();
            CP_WAIT1();
        } else {
            CP_WAIT0();
        }
        __syncthreads();

        const uint32_t sA = sb + ((c & 1) ? SM_A1 : SM_A0);
        const uint32_t sB = sb + ((c & 1) ? SM_B1 : SM_B0);

#pragma unroll
        for (int kk = 0; kk < 4; ++kk) {
            const int kb = kk * 32;
            uint32_t afr[4][4];
#pragma unroll
            for (int mt = 0; mt < 4; ++mt) {
                uint32_t addr = sA + swz128((uint32_t)((wm * 64 + mt * 16 + a_row) * 128
                                                       + kb + a_colb));
                LDSM_X4(afr[mt][0], afr[mt][1], afr[mt][2], afr[mt][3], addr);
            }
            uint32_t bfr[4][4];
#pragma unroll
            for (int nb2 = 0; nb2 < 4; ++nb2) {
                uint32_t addr = sB + swz128((uint32_t)((wn * 64 + nb2 * 16 + b_row) * 128
                                                       + kb + b_colb));
                LDSM_X4(bfr[nb2][0], bfr[nb2][1], bfr[nb2][2], bfr[nb2][3], addr);
            }
#pragma unroll
            for (int mt = 0; mt < 4; ++mt)
#pragma unroll
                for (int nb = 0; nb < 8; ++nb) {
                    const uint32_t b0 = bfr[nb >> 1][(nb & 1) * 2 + 0];
                    const uint32_t b1 = bfr[nb >> 1][(nb & 1) * 2 + 1];
                    MMA16816(acc[mt][nb], afr[mt], b0, b1);
                }
        }
        __syncthreads();
    }

    // epilogue: direct fp32 stores (float2 per half-tile)
    const int qr = lane >> 2;          // 0..7
    const int qc = (lane & 3) * 2;     // 0,2,4,6
#pragma unroll
    for (int mt = 0; mt < 4; ++mt) {
        const int row0 = bm + wm * 64 + mt * 16 + qr;
        const int row1 = row0 + 8;
        const bool ok0 = !CHECK_M || row0 < M;
        const bool ok1 = !CHECK_M || row1 < M;
#pragma unroll
        for (int nb = 0; nb < 8; ++nb) {
            const int col = bn + wn * 64 + nb * 8 + qc;
            float bx = 0.f, by = 0.f;
            if (BIAS) { bx = bias[col]; by = bias[col + 1]; }
            if (ok0) {
                float2 v = make_float2(acc[mt][nb][0] + bx, acc[mt][nb][1] + by);
                *(float2*)(C + (size_t)row0 * ldC + col) = v;
            }
            if (ok1) {
                float2 v = make_float2(acc[mt][nb][2] + bx, acc[mt][nb][3] + by);
                *(float2*)(C + (size_t)row1 * ldC + col) = v;
            }
        }
    }
}

// ============================================================
// A split: fp32 [M,K] -> bf16 [M, 2K] = [hi | lo]
// ============================================================
__global__ void asplit_kernel(const float* __restrict__ X, __nv_bfloat16* __restrict__ out, int K)
{
    int idx4 = (blockIdx.x * 256 + threadIdx.x) * 4;
    int row = idx4 / K;
    int col = idx4 - row * K;
    float4 v = *(const float4*)(X + (size_t)row * K + col);
    __nv_bfloat162 h0 = __floats2bfloat162_rn(v.x, v.y);
    __nv_bfloat162 h1 = __floats2bfloat162_rn(v.z, v.w);
    float lx = v.x - __bfloat162float(__low2bfloat16(h0));
    float ly = v.y - __bfloat162float(__high2bfloat16(h0));
    float lz = v.z - __bfloat162float(__low2bfloat16(h1));
    float lw = v.w - __bfloat162float(__high2bfloat16(h1));
    __nv_bfloat162 l0 = __floats2bfloat162_rn(lx, ly);
    __nv_bfloat162 l1 = __floats2bfloat162_rn(lz, lw);
    __nv_bfloat16* oh = out + (size_t)row * 2 * K + col;
    *(__nv_bfloat162*)(oh)     = h0;
    *(__nv_bfloat162*)(oh + 2) = h1;
    __nv_bfloat16* ol = oh + K;
    *(__nv_bfloat162*)(ol)     = l0;
    *(__nv_bfloat162*)(ol + 2) = l1;
}

// ============================================================
// Weight transpose+split: fp32 W[K,N] -> bf16 W'[rowoff+n][3K] = [hi|hi|lo]
// ============================================================
__global__ void wsplit_kernel(const float* __restrict__ W, __nv_bfloat16* __restrict__ out,
                              int K, int N, int ld3, int rowoff)
{
    __shared__ float t[32][33];
    int k0 = blockIdx.x * 32, n0 = blockIdx.y * 32;
    int tx = threadIdx.x & 31, ty = threadIdx.x >> 5;
#pragma unroll
    for (int r = 0; r < 4; ++r)
        t[ty + r * 8][tx] = W[(size_t)(k0 + ty + r * 8) * N + n0 + tx];
    __syncthreads();
#pragma unroll
    for (int r = 0; r < 4; ++r) {
        int n = n0 + ty + r * 8;
        int k = k0 + tx;
        float x = t[tx][ty + r * 8];
        __nv_bfloat16 hi = __float2bfloat16(x);
        __nv_bfloat16 lo = __float2bfloat16(x - __bfloat162float(hi));
        __nv_bfloat16* rowp = out + (size_t)(rowoff + n) * ld3;
        rowp[k]         = hi;
        rowp[K + k]     = hi;
        rowp[2 * K + k] = lo;
    }
}

// ============================================================
// Boost
// ============================================================
__global__ void boost_kernel(const float* __restrict__ mask)
{
    __shared__ float red[128];
    float s = 0.f;
    for (int i = threadIdx.x; i < SS; i += 128) s += mask[i];
    red[threadIdx.x] = s;
    __syncthreads();
    for (int o = 64; o > 0; o >>= 1) {
        if (threadIdx.x < o) red[threadIdx.x] += red[threadIdx.x + o];
        __syncthreads();
    }
    if (threadIdx.x == 0) {
        float ratio = red[0] * (1.0f / (float)SS);
        float b = 1.0f;
        if (ratio > 1e-6f && ratio < 0.1f)
            b = fminf(1.0f + (0.1f - ratio) * 30.0f, 4.0f);
        g_boost = b;
    }
}

// ============================================================
// Fused dual-branch attention (fp32), K/V from fused g_KV
// ============================================================
#define QSTR 68
#define KSTR 84
#define PSTR 80
#define ATT_SMEM_FLOATS (128*QSTR + 64*KSTR + 128*PSTR + 80*64)
#define ATT_SMEM_BYTES  (ATT_SMEM_FLOATS * 4)

__global__ __launch_bounds__(256, 1)
void attn_kernel(const float* __restrict__ msk)
{
    extern __shared__ float sm[];
    float* Qs = sm;
    float* Ks = Qs + 128 * QSTR;
    float* Ps = Ks + 64 * KSTR;
    float* Vs = Ps + 128 * PSTR;

    const int tid = threadIdx.x;
    const int tx  = tid & 15;
    const int ty  = tid >> 4;
    const int r0  = ty << 3;
    const int t0  = tx << 2;
    const int c0  = tx << 2;
    const int b   = blockIdx.y / NH;
    const int h   = blockIdx.y % NH;
    const int s0  = blockIdx.x * 128;

    {
        const float* qb = g_Q + (size_t)(b * SS + s0) * DD + h * HDIM;
#pragma unroll
        for (int k = 0; k < 8; ++k) {
            int fidx = tid + k * 256;
            int r  = fidx >> 4;
            int d4 = (fidx & 15) << 2;
            float4 v = *(const float4*)(qb + (size_t)r * DD + d4);
            *(float4*)(Qs + r * QSTR + d4) = v;
        }
    }

    float o1[8][4];

    for (int br = 0; br < 2; ++br) {
        const float* kb = g_KV + (size_t)(b * SKV) * KVLD + (br ? 2560 : 0) + h * HDIM;
        const float* vb = kb + 1280;

        for (int idx = tid; idx < 80 * 64; idx += 256) {
            int t = idx >> 6, d = idx & 63;
            Ks[d * KSTR + t] = (t < SKV) ? kb[(size_t)t * KVLD + d] : 0.f;
        }
        __syncthreads();

        float acc[8][5];
#pragma unroll
        for (int i = 0; i < 8; ++i)
#pragma unroll
            for (int j = 0; j < 5; ++j) acc[i][j] = 0.f;

#pragma unroll 2
        for (int d = 0; d < 64; ++d) {
            float4 k4 = *(const float4*)(Ks + d * KSTR + t0);
            float  k5 = Ks[d * KSTR + 64 + tx];
            float kr[5] = {k4.x, k4.y, k4.z, k4.w, k5};
#pragma unroll
            for (int i = 0; i < 8; ++i) {
                float q = Qs[(r0 + i) * QSTR + d];
#pragma unroll
                for (int j = 0; j < 5; ++j)
                    acc[i][j] = fmaf(q, kr[j], acc[i][j]);
            }
        }

        const bool pad5 = (64 + tx) >= SKV;
#pragma unroll
        for (int i = 0; i < 8; ++i) {
#pragma unroll
            for (int j = 0; j < 5; ++j) acc[i][j] *= 0.125f;
            if (pad5) acc[i][4] = -INFINITY;
            float m = acc[i][0];
#pragma unroll
            for (int j = 1; j < 5; ++j) m = fmaxf(m, acc[i][j]);
#pragma unroll
            for (int o = 1; o < 16; o <<= 1)
                m = fmaxf(m, __shfl_xor_sync(0xffffffffu, m, o));
            float s = 0.f;
#pragma unroll
            for (int j = 0; j < 5; ++j) { acc[i][j] = __expf(acc[i][j] - m); s += acc[i][j]; }
#pragma unroll
            for (int o = 1; o < 16; o <<= 1)
                s += __shfl_xor_sync(0xffffffffu, s, o);
            float inv = 1.0f / s;
            Ps[(r0 + i) * PSTR + t0 + 0] = acc[i][0] * inv;
            Ps[(r0 + i) * PSTR + t0 + 1] = acc[i][1] * inv;
            Ps[(r0 + i) * PSTR + t0 + 2] = acc[i][2] * inv;
            Ps[(r0 + i) * PSTR + t0 + 3] = acc[i][3] * inv;
            Ps[(r0 + i) * PSTR + 64 + tx] = acc[i][4] * inv;
        }

        for (int idx = tid; idx < 80 * 64; idx += 256) {
            int t = idx >> 6, d = idx & 63;
            Vs[t * 64 + d] = (t < SKV) ? vb[(size_t)t * KVLD + d] : 0.f;
        }
        __syncthreads();

        float acc2[8][4];
#pragma unroll
        for (int i = 0; i < 8; ++i)
#pragma unroll
            for (int c = 0; c < 4; ++c) acc2[i][c] = 0.f;

        for (int t = 0; t < SKV; ++t) {
            float4 v4 = *(const float4*)(Vs + t * 64 + c0);
#pragma unroll
            for (int i = 0; i < 8; ++i) {
                float p = Ps[(r0 + i) * PSTR + t];
                acc2[i][0] = fmaf(p, v4.x, acc2[i][0]);
                acc2[i][1] = fmaf(p, v4.y, acc2[i][1]);
                acc2[i][2] = fmaf(p, v4.z, acc2[i][2]);
                acc2[i][3] = fmaf(p, v4.w, acc2[i][3]);
            }
        }

        if (br == 0) {
#pragma unroll
            for (int i = 0; i < 8; ++i)
#pragma unroll
                for (int c = 0; c < 4; ++c) o1[i][c] = acc2[i][c];
        } else {
            const float boost = g_boost;
            float* cb = g_comb + (size_t)(b * SS + s0) * DD + h * HDIM;
#pragma unroll
            for (int i = 0; i < 8; ++i) {
                float mb = msk[s0 + r0 + i] * boost;
                float4 o;
                o.x = o1[i][0] + mb * acc2[i][0];
                o.y = o1[i][1] + mb * acc2[i][1];
                o.z = o1[i][2] + mb * acc2[i][2];
                o.w = o1[i][3] + mb * acc2[i][3];
                *(float4*)(cb + (size_t)(r0 + i) * DD + c0) = o;
            }
        }
    }
}

// ============================================================
// launch
// ============================================================
extern "C" void kernel_launch(void* const* d_in, const int* in_sizes, int n_in,
                              void* d_out, int out_size)
{
    const float* hs   = (const float*)d_in[0];
    const float* ehs  = (const float*)d_in[1];
    const float* msk  = (const float*)d_in[2];
    const float* Wq   = (const float*)d_in[3];
    const float* Wk   = (const float*)d_in[4];
    const float* Wv   = (const float*)d_in[5];
    const float* Wkip = (const float*)d_in[6];
    const float* Wvip = (const float*)d_in[7];
    const float* Wo   = (const float*)d_in[8];
    const float* bo   = (const float*)d_in[9];
    float* out = (float*)d_out;

    __nv_bfloat16 *gAs, *gW3, *gWkv, *gAkv;
    float *gq, *gkv, *gc;
    cudaGetSymbolAddress((void**)&gAs,  g_Asplit);
    cudaGetSymbolAddress((void**)&gW3,  g_W3);
    cudaGetSymbolAddress((void**)&gWkv, g_Wkv3);
    cudaGetSymbolAddress((void**)&gAkv, g_Akv);
    cudaGetSymbolAddress((void**)&gq,   g_Q);
    cudaGetSymbolAddress((void**)&gkv,  g_KV);
    cudaGetSymbolAddress((void**)&gc,   g_comb);

    cudaFuncSetAttribute(hmma_gemm<false, false>,
                         cudaFuncAttributeMaxDynamicSharedMemorySize, GEMM_SMEM);
    cudaFuncSetAttribute(hmma_gemm<true, false>,
                         cudaFuncAttributeMaxDynamicSharedMemorySize, GEMM_SMEM);
    cudaFuncSetAttribute(hmma_gemm<false, true>,
                         cudaFuncAttributeMaxDynamicSharedMemorySize, GEMM_SMEM);
    cudaFuncSetAttribute(attn_kernel,
                         cudaFuncAttributeMaxDynamicSharedMemorySize, ATT_SMEM_BYTES);

    // ---- Q projection ----
    asplit_kernel<<<(MQ * DD) / 1024, 256>>>(hs, gAs, DD);
    wsplit_kernel<<<dim3(DD / 32, DD / 32), 256>>>(Wq, gW3, DD, DD, 3 * DD, 0);
    hmma_gemm<false, false><<<dim3(MQ / 128, DD / 128), 128, GEMM_SMEM>>>(
        gAs, 2 * DD, 40, gW3, 3 * DD, 60, nullptr, gq, DD, MQ);

    // ---- fused K/V/Kip/Vip projections ----
    asplit_kernel<<<(MKV * CDIM) / 1024, 256>>>(ehs, gAkv, CDIM);
    wsplit_kernel<<<dim3(CDIM / 32, DD / 32), 256>>>(Wk,   gWkv, CDIM, DD, 3 * CDIM, 0);
    wsplit_kernel<<<dim3(CDIM / 32, DD / 32), 256>>>(Wv,   gWkv, CDIM, DD, 3 * CDIM, 1280);
    wsplit_kernel<<<dim3(CDIM / 32, DD / 32), 256>>>(Wkip, gWkv, CDIM, DD, 3 * CDIM, 2560);
    wsplit_kernel<<<dim3(CDIM / 32, DD / 32), 256>>>(Wvip, gWkv, CDIM, DD, 3 * CDIM, 3840);
    hmma_gemm<true, false><<<dim3(3, KVLD / 128), 128, GEMM_SMEM>>>(
        gAkv, 2 * CDIM, 64, gWkv, 3 * CDIM, 96, nullptr, gkv, KVLD, MKV);

    // ---- boost + attention ----
    boost_kernel<<<1, 128>>>(msk);
    attn_kernel<<<dim3(SS / 128, BB * NH), 256, ATT_SMEM_BYTES>>>(msk);

    // ---- output projection (+bias) ----
    asplit_kernel<<<(MQ * DD) / 1024, 256>>>(gc, gAs, DD);
    wsplit_kernel<<<dim3(DD / 32, DD / 32), 256>>>(Wo, gW3, DD, DD, 3 * DD, 0);
    hmma_gemm<false, true><<<dim3(MQ / 128, DD / 128), 128, GEMM_SMEM>>>(
        gAs, 2 * DD, 40, gW3, 3 * DD, 60, bo, out, DD, MQ);
}

// round 9
// speedup vs baseline: 3.6332x; 1.2399x over previous
#include <cuda_runtime.h>
#include <cuda_bf16.h>
#include <math.h>
#include <stdint.h>

// ---------------- problem constants ----------------
#define BB   4
#define SS   4096
#define DD   1280
#define SKV  77
#define CDIM 2048
#define NH   20
#define HDIM 64
#define MQ   (BB*SS)    // 16384
#define MKV  (BB*SKV)   // 308
#define KVLD 5120       // fused KV output row stride: [K|V|Kip|Vip]

// ---------------- scratch (all fp32, tf32-rounded where noted) ----------------
__device__ float g_A    [(size_t)MQ * DD];        // rna(hidden_states)
__device__ float g_Aehs [(size_t)MKV * CDIM];     // rna(encoder_hidden_states)
__device__ float g_Wt   [(size_t)DD * DD];        // rna(W^T), Wq then Wo (sequential reuse)
__device__ float g_Wkvt [(size_t)4 * DD * CDIM];  // rna([Wk|Wv|Wkip|Wvip]^T)
__device__ float g_Q    [(size_t)MQ * DD];
__device__ float g_KV   [(size_t)MKV * KVLD];
__device__ float g_comb [(size_t)MQ * DD];        // rna-rounded by attention epilogue
__device__ float g_boost;

// ---------------- helpers ----------------
__device__ __forceinline__ uint32_t swz128(uint32_t b) { return b ^ ((b >> 3) & 0x70); }

__device__ __forceinline__ float tf32_rna(float x) {
    float r;
    asm("cvt.rna.tf32.f32 %0, %1;" : "=f"(r) : "f"(x));
    return r;
}

#define CP_COMMIT()  asm volatile("cp.async.commit_group;" ::: "memory")
#define CP_WAIT1()   asm volatile("cp.async.wait_group 1;" ::: "memory")
#define CP_WAIT0()   asm volatile("cp.async.wait_group 0;" ::: "memory")

#define LDSM_X4(r0,r1,r2,r3,addr) \
    asm volatile("ldmatrix.sync.aligned.m8n8.x4.shared.b16 {%0,%1,%2,%3}, [%4];" \
                 : "=r"(r0), "=r"(r1), "=r"(r2), "=r"(r3) : "r"(addr))

// tf32 m16n8k8: a = 4 regs, b = 2 regs, fp32 accum
#define MMA16888(d, a, b0, b1) \
    asm volatile("mma.sync.aligned.m16n8k8.row.col.f32.tf32.tf32.f32 " \
                 "{%0,%1,%2,%3}, {%4,%5,%6,%7}, {%8,%9}, {%0,%1,%2,%3};" \
                 : "+f"((d)[0]), "+f"((d)[1]), "+f"((d)[2]), "+f"((d)[3]) \
                 : "r"((a)[0]), "r"((a)[1]), "r"((a)[2]), "r"((a)[3]), \
                   "r"(b0), "r"(b1))

// ============================================================
// TF32 GEMM: CTA 128x128, 4 warps (2x2 of 64x64), K-chunk 32 fp32 (128B rows),
// double-buffered cp.async + ldmatrix(b16 view), SW128 swizzle.
//   A: [M, K] fp32 (tf32-rounded), row-major
//   B: [N, K] fp32 (tf32-rounded), K-major (pre-transposed)
// ============================================================
#define SM_A0   0
#define SM_B0   16384
#define SM_A1   32768
#define SM_B1   49152
#define GEMM_SMEM 65536

template<bool CHECK_M>
__device__ __forceinline__ void stage_chunk(uint32_t sb, uint32_t aoff, uint32_t boff,
                                            const char* ab, int ldAb,
                                            const char* bb, int ldBb,
                                            int bm, int M, int tid)
{
#pragma unroll
    for (int i = 0; i < 8; ++i) {
        int idx = tid + i * 128;
        int r = idx >> 3, seg = idx & 7;
        uint32_t d = sb + aoff + swz128((uint32_t)(r * 128 + seg * 16));
        const char* s = ab + (size_t)r * ldAb + seg * 16;
        int sz = (!CHECK_M || (bm + r) < M) ? 16 : 0;
        asm volatile("cp.async.cg.shared.global [%0], [%1], 16, %2;"
                     :: "r"(d), "l"(s), "r"(sz) : "memory");
    }
#pragma unroll
    for (int i = 0; i < 8; ++i) {
        int idx = tid + i * 128;
        int r = idx >> 3, seg = idx & 7;
        uint32_t d = sb + boff + swz128((uint32_t)(r * 128 + seg * 16));
        const char* s = bb + (size_t)r * ldBb + seg * 16;
        asm volatile("cp.async.cg.shared.global [%0], [%1], 16;"
                     :: "r"(d), "l"(s) : "memory");
    }
}

template<bool CHECK_M, bool BIAS>
__global__ __launch_bounds__(128, 2)
void tf32_gemm(const float* __restrict__ A, int ldA,
               const float* __restrict__ Bw, int ldB, int NC,
               const float* __restrict__ bias,
               float* __restrict__ C, int ldC, int M)
{
    extern __shared__ char smem_raw[];
    const uint32_t sb = (uint32_t)__cvta_generic_to_shared(smem_raw);
    const int tid  = threadIdx.x;
    const int lane = tid & 31;
    const int wid  = tid >> 5;
    const int wm   = wid & 1;
    const int wn   = wid >> 1;
    const int bm   = blockIdx.x * 128;
    const int bn   = blockIdx.y * 128;

    const int ldAb = ldA * 4;        // byte strides (fp32)
    const int ldBb = ldB * 4;
    const char* Abase = (const char*)A + (size_t)bm * ldAb;
    const char* Bbase = (const char*)Bw + (size_t)bn * ldBb;

    float acc[4][8][4];
#pragma unroll
    for (int mt = 0; mt < 4; ++mt)
#pragma unroll
        for (int nb = 0; nb < 8; ++nb)
#pragma unroll
            for (int e = 0; e < 4; ++e) acc[mt][nb][e] = 0.f;

    // ldmatrix lane address components (16B segments inside 128B rows)
    const int a_row  = (lane & 7) + ((lane & 8) ? 8 : 0);
    const int a_colb = (lane & 16) ? 16 : 0;
    const int b_row  = (lane & 7) + ((lane & 16) ? 8 : 0);
    const int b_colb = (lane & 8) ? 16 : 0;

    // prologue: chunk 0 -> buf 0
    stage_chunk<CHECK_M>(sb, SM_A0, SM_B0, Abase, ldAb, Bbase, ldBb, bm, M, tid);
    CP_COMMIT();

    for (int c = 0; c < NC; ++c) {
        const bool more = (c + 1) < NC;
        if (more) {
            const int cn = c + 1;
            const uint32_t aoff = (cn & 1) ? SM_A1 : SM_A0;
            const uint32_t boff = (cn & 1) ? SM_B1 : SM_B0;
            stage_chunk<CHECK_M>(sb, aoff, boff,
                                 Abase + (size_t)cn * 128, ldAb,
                                 Bbase + (size_t)cn * 128, ldBb, bm, M, tid);
            CP_COMMIT();
            CP_WAIT1();
        } else {
            CP_WAIT0();
        }
        __syncthreads();

        const uint32_t sA = sb + ((c & 1) ? SM_A1 : SM_A0);
        const uint32_t sB = sb + ((c & 1) ? SM_B1 : SM_B0);

#pragma unroll
        for (int kk = 0; kk < 4; ++kk) {     // 4 x k8 (32B each)
            const int kb = kk * 32;
            uint32_t afr[4][4];
#pragma unroll
            for (int mt = 0; mt < 4; ++mt) {
                uint32_t addr = sA + swz128((uint32_t)((wm * 64 + mt * 16 + a_row) * 128
                                                       + kb + a_colb));
                LDSM_X4(afr[mt][0], afr[mt][1], afr[mt][2], afr[mt][3], addr);
            }
            uint32_t bfr[4][4];
#pragma unroll
            for (int nb2 = 0; nb2 < 4; ++nb2) {
                uint32_t addr = sB + swz128((uint32_t)((wn * 64 + nb2 * 16 + b_row) * 128
                                                       + kb + b_colb));
                LDSM_X4(bfr[nb2][0], bfr[nb2][1], bfr[nb2][2], bfr[nb2][3], addr);
            }
#pragma unroll
            for (int mt = 0; mt < 4; ++mt)
#pragma unroll
                for (int nb = 0; nb < 8; ++nb) {
                    const uint32_t b0 = bfr[nb >> 1][(nb & 1) * 2 + 0];
                    const uint32_t b1 = bfr[nb >> 1][(nb & 1) * 2 + 1];
                    MMA16888(acc[mt][nb], afr[mt], b0, b1);
                }
        }
        __syncthreads();
    }

    // epilogue
    const int qr = lane >> 2;
    const int qc = (lane & 3) * 2;
#pragma unroll
    for (int mt = 0; mt < 4; ++mt) {
        const int row0 = bm + wm * 64 + mt * 16 + qr;
        const int row1 = row0 + 8;
        const bool ok0 = !CHECK_M || row0 < M;
        const bool ok1 = !CHECK_M || row1 < M;
#pragma unroll
        for (int nb = 0; nb < 8; ++nb) {
            const int col = bn + wn * 64 + nb * 8 + qc;
            float bx = 0.f, by = 0.f;
            if (BIAS) { bx = bias[col]; by = bias[col + 1]; }
            if (ok0) {
                float2 v = make_float2(acc[mt][nb][0] + bx, acc[mt][nb][1] + by);
                *(float2*)(C + (size_t)row0 * ldC + col) = v;
            }
            if (ok1) {
                float2 v = make_float2(acc[mt][nb][2] + bx, acc[mt][nb][3] + by);
                *(float2*)(C + (size_t)row1 * ldC + col) = v;
            }
        }
    }
}

// ============================================================
// A convert: fp32 -> tf32-rounded fp32 (elementwise)
// ============================================================
__global__ void aconv_kernel(const float* __restrict__ X, float* __restrict__ out)
{
    int idx4 = (blockIdx.x * 256 + threadIdx.x) * 4;
    float4 v = *(const float4*)(X + idx4);
    v.x = tf32_rna(v.x); v.y = tf32_rna(v.y);
    v.z = tf32_rna(v.z); v.w = tf32_rna(v.w);
    *(float4*)(out + idx4) = v;
}

// ============================================================
// Weight transpose + rna: fp32 W[K,N] -> fp32 W'[rowoff+n][k]
// ============================================================
__global__ void wtrans_kernel(const float* __restrict__ W, float* __restrict__ out,
                              int K, int N, int ldo, int rowoff)
{
    __shared__ float t[32][33];
    int k0 = blockIdx.x * 32, n0 = blockIdx.y * 32;
    int tx = threadIdx.x & 31, ty = threadIdx.x >> 5;
#pragma unroll
    for (int r = 0; r < 4; ++r)
        t[ty + r * 8][tx] = W[(size_t)(k0 + ty + r * 8) * N + n0 + tx];
    __syncthreads();
#pragma unroll
    for (int r = 0; r < 4; ++r) {
        int n = n0 + ty + r * 8;
        int k = k0 + tx;
        out[(size_t)(rowoff + n) * ldo + k] = tf32_rna(t[tx][ty + r * 8]);
    }
}

// ============================================================
// Boost
// ============================================================
__global__ void boost_kernel(const float* __restrict__ mask)
{
    __shared__ float red[128];
    float s = 0.f;
    for (int i = threadIdx.x; i < SS; i += 128) s += mask[i];
    red[threadIdx.x] = s;
    __syncthreads();
    for (int o = 64; o > 0; o >>= 1) {
        if (threadIdx.x < o) red[threadIdx.x] += red[threadIdx.x + o];
        __syncthreads();
    }
    if (threadIdx.x == 0) {
        float ratio = red[0] * (1.0f / (float)SS);
        float b = 1.0f;
        if (ratio > 1e-6f && ratio < 0.1f)
            b = fminf(1.0f + (0.1f - ratio) * 30.0f, 4.0f);
        g_boost = b;
    }
}

// ============================================================
// Fused dual-branch attention (fp32), rna-rounded output for tf32 out-proj
// ============================================================
#define QSTR 68
#define KSTR 84
#define PSTR 80
#define ATT_SMEM_FLOATS (128*QSTR + 64*KSTR + 128*PSTR + 80*64)
#define ATT_SMEM_BYTES  (ATT_SMEM_FLOATS * 4)

__global__ __launch_bounds__(256, 1)
void attn_kernel(const float* __restrict__ msk)
{
    extern __shared__ float sm[];
    float* Qs = sm;
    float* Ks = Qs + 128 * QSTR;
    float* Ps = Ks + 64 * KSTR;
    float* Vs = Ps + 128 * PSTR;

    const int tid = threadIdx.x;
    const int tx  = tid & 15;
    const int ty  = tid >> 4;
    const int r0  = ty << 3;
    const int t0  = tx << 2;
    const int c0  = tx << 2;
    const int b   = blockIdx.y / NH;
    const int h   = blockIdx.y % NH;
    const int s0  = blockIdx.x * 128;

    {
        const float* qb = g_Q + (size_t)(b * SS + s0) * DD + h * HDIM;
#pragma unroll
        for (int k = 0; k < 8; ++k) {
            int fidx = tid + k * 256;
            int r  = fidx >> 4;
            int d4 = (fidx & 15) << 2;
            float4 v = *(const float4*)(qb + (size_t)r * DD + d4);
            *(float4*)(Qs + r * QSTR + d4) = v;
        }
    }

    float o1[8][4];

    for (int br = 0; br < 2; ++br) {
        const float* kb = g_KV + (size_t)(b * SKV) * KVLD + (br ? 2560 : 0) + h * HDIM;
        const float* vb = kb + 1280;

        for (int idx = tid; idx < 80 * 64; idx += 256) {
            int t = idx >> 6, d = idx & 63;
            Ks[d * KSTR + t] = (t < SKV) ? kb[(size_t)t * KVLD + d] : 0.f;
        }
        __syncthreads();

        float acc[8][5];
#pragma unroll
        for (int i = 0; i < 8; ++i)
#pragma unroll
            for (int j = 0; j < 5; ++j) acc[i][j] = 0.f;

#pragma unroll 2
        for (int d = 0; d < 64; ++d) {
            float4 k4 = *(const float4*)(Ks + d * KSTR + t0);
            float  k5 = Ks[d * KSTR + 64 + tx];
            float kr[5] = {k4.x, k4.y, k4.z, k4.w, k5};
#pragma unroll
            for (int i = 0; i < 8; ++i) {
                float q = Qs[(r0 + i) * QSTR + d];
#pragma unroll
                for (int j = 0; j < 5; ++j)
                    acc[i][j] = fmaf(q, kr[j], acc[i][j]);
            }
        }

        const bool pad5 = (64 + tx) >= SKV;
#pragma unroll
        for (int i = 0; i < 8; ++i) {
#pragma unroll
            for (int j = 0; j < 5; ++j) acc[i][j] *= 0.125f;
            if (pad5) acc[i][4] = -INFINITY;
            float m = acc[i][0];
#pragma unroll
            for (int j = 1; j < 5; ++j) m = fmaxf(m, acc[i][j]);
#pragma unroll
            for (int o = 1; o < 16; o <<= 1)
                m = fmaxf(m, __shfl_xor_sync(0xffffffffu, m, o));
            float s = 0.f;
#pragma unroll
            for (int j = 0; j < 5; ++j) { acc[i][j] = __expf(acc[i][j] - m); s += acc[i][j]; }
#pragma unroll
            for (int o = 1; o < 16; o <<= 1)
                s += __shfl_xor_sync(0xffffffffu, s, o);
            float inv = 1.0f / s;
            Ps[(r0 + i) * PSTR + t0 + 0] = acc[i][0] * inv;
            Ps[(r0 + i) * PSTR + t0 + 1] = acc[i][1] * inv;
            Ps[(r0 + i) * PSTR + t0 + 2] = acc[i][2] * inv;
            Ps[(r0 + i) * PSTR + t0 + 3] = acc[i][3] * inv;
            Ps[(r0 + i) * PSTR + 64 + tx] = acc[i][4] * inv;
        }

        for (int idx = tid; idx < 80 * 64; idx += 256) {
            int t = idx >> 6, d = idx & 63;
            Vs[t * 64 + d] = (t < SKV) ? vb[(size_t)t * KVLD + d] : 0.f;
        }
        __syncthreads();

        float acc2[8][4];
#pragma unroll
        for (int i = 0; i < 8; ++i)
#pragma unroll
            for (int c = 0; c < 4; ++c) acc2[i][c] = 0.f;

        for (int t = 0; t < SKV; ++t) {
            float4 v4 = *(const float4*)(Vs + t * 64 + c0);
#pragma unroll
            for (int i = 0; i < 8; ++i) {
                float p = Ps[(r0 + i) * PSTR + t];
                acc2[i][0] = fmaf(p, v4.x, acc2[i][0]);
                acc2[i][1] = fmaf(p, v4.y, acc2[i][1]);
                acc2[i][2] = fmaf(p, v4.z, acc2[i][2]);
                acc2[i][3] = fmaf(p, v4.w, acc2[i][3]);
            }
        }

        if (br == 0) {
#pragma unroll
            for (int i = 0; i < 8; ++i)
#pragma unroll
                for (int c = 0; c < 4; ++c) o1[i][c] = acc2[i][c];
        } else {
            const float boost = g_boost;
            float* cb = g_comb + (size_t)(b * SS + s0) * DD + h * HDIM;
#pragma unroll
            for (int i = 0; i < 8; ++i) {
                float mb = msk[s0 + r0 + i] * boost;
                float4 o;
                o.x = tf32_rna(o1[i][0] + mb * acc2[i][0]);
                o.y = tf32_rna(o1[i][1] + mb * acc2[i][1]);
                o.z = tf32_rna(o1[i][2] + mb * acc2[i][2]);
                o.w = tf32_rna(o1[i][3] + mb * acc2[i][3]);
                *(float4*)(cb + (size_t)(r0 + i) * DD + c0) = o;
            }
        }
    }
}

// ============================================================
// launch
// ============================================================
extern "C" void kernel_launch(void* const* d_in, const int* in_sizes, int n_in,
                              void* d_out, int out_size)
{
    const float* hs   = (const float*)d_in[0];
    const float* ehs  = (const float*)d_in[1];
    const float* msk  = (const float*)d_in[2];
    const float* Wq   = (const float*)d_in[3];
    const float* Wk   = (const float*)d_in[4];
    const float* Wv   = (const float*)d_in[5];
    const float* Wkip = (const float*)d_in[6];
    const float* Wvip = (const float*)d_in[7];
    const float* Wo   = (const float*)d_in[8];
    const float* bo   = (const float*)d_in[9];
    float* out = (float*)d_out;

    float *gA, *gAe, *gWt, *gWkvt, *gq, *gkv, *gc;
    cudaGetSymbolAddress((void**)&gA,    g_A);
    cudaGetSymbolAddress((void**)&gAe,   g_Aehs);
    cudaGetSymbolAddress((void**)&gWt,   g_Wt);
    cudaGetSymbolAddress((void**)&gWkvt, g_Wkvt);
    cudaGetSymbolAddress((void**)&gq,    g_Q);
    cudaGetSymbolAddress((void**)&gkv,   g_KV);
    cudaGetSymbolAddress((void**)&gc,    g_comb);

    cudaFuncSetAttribute(tf32_gemm<false, false>,
                         cudaFuncAttributeMaxDynamicSharedMemorySize, GEMM_SMEM);
    cudaFuncSetAttribute(tf32_gemm<true, false>,
                         cudaFuncAttributeMaxDynamicSharedMemorySize, GEMM_SMEM);
    cudaFuncSetAttribute(tf32_gemm<false, true>,
                         cudaFuncAttributeMaxDynamicSharedMemorySize, GEMM_SMEM);
    cudaFuncSetAttribute(attn_kernel,
                         cudaFuncAttributeMaxDynamicSharedMemorySize, ATT_SMEM_BYTES);

    // ---- Q projection ----
    aconv_kernel<<<(MQ * DD) / 1024, 256>>>(hs, gA);
    wtrans_kernel<<<dim3(DD / 32, DD / 32), 256>>>(Wq, gWt, DD, DD, DD, 0);
    tf32_gemm<false, false><<<dim3(MQ / 128, DD / 128), 128, GEMM_SMEM>>>(
        gA, DD, gWt, DD, DD / 32, nullptr, gq, DD, MQ);

    // ---- fused K/V/Kip/Vip projections ----
    aconv_kernel<<<(MKV * CDIM) / 1024, 256>>>(ehs, gAe);
    wtrans_kernel<<<dim3(CDIM / 32, DD / 32), 256>>>(Wk,   gWkvt, CDIM, DD, CDIM, 0);
    wtrans_kernel<<<dim3(CDIM / 32, DD / 32), 256>>>(Wv,   gWkvt, CDIM, DD, CDIM, 1280);
    wtrans_kernel<<<dim3(CDIM / 32, DD / 32), 256>>>(Wkip, gWkvt, CDIM, DD, CDIM, 2560);
    wtrans_kernel<<<dim3(CDIM / 32, DD / 32), 256>>>(Wvip, gWkvt, CDIM, DD, CDIM, 3840);
    tf32_gemm<true, false><<<dim3(3, KVLD / 128), 128, GEMM_SMEM>>>(
        gAe, CDIM, gWkvt, CDIM, CDIM / 32, nullptr, gkv, KVLD, MKV);

    // ---- boost + attention (writes rna-rounded g_comb) ----
    boost_kernel<<<1, 128>>>(msk);
    attn_kernel<<<dim3(SS / 128, BB * NH), 256, ATT_SMEM_BYTES>>>(msk);

    // ---- output projection (+bias) ----
    wtrans_kernel<<<dim3(DD / 32, DD / 32), 256>>>(Wo, gWt, DD, DD, DD, 0);
    tf32_gemm<false, true><<<dim3(MQ / 128, DD / 128), 128, GEMM_SMEM>>>(
        gc, DD, gWt, DD, DD / 32, bo, out, DD, MQ);
}

// round 11
// speedup vs baseline: 5.3993x; 1.4861x over previous
#include <cuda_runtime.h>
#include <cuda_bf16.h>
#include <math.h>
#include <stdint.h>

// ---------------- problem constants ----------------
#define BB   4
#define SS   4096
#define DD   1280
#define SKV  77
#define CDIM 2048
#define NH   20
#define HDIM 64
#define MQ   (BB*SS)    // 16384
#define MKV  (BB*SKV)   // 308
#define KVLD 5120       // fused KV output row stride: [K|V|Kip|Vip]

// ---------------- scratch ----------------
__device__ float g_Wt   [(size_t)DD * DD];        // rna(W^T), Wq then Wo
__device__ float g_Wkvt [(size_t)4 * DD * CDIM];  // rna([Wk|Wv|Wkip|Wvip]^T)
__device__ float g_Q    [(size_t)MQ * DD];
__device__ float g_KV   [(size_t)MKV * KVLD];
__device__ float g_comb [(size_t)MQ * DD];
__device__ float g_boost;

// ---------------- helpers ----------------
__device__ __forceinline__ uint32_t swz128(uint32_t b) { return b ^ ((b >> 3) & 0x70); }

__device__ __forceinline__ float tf32_rna(float x) {
    float r;
    asm("cvt.rna.tf32.f32 %0, %1;" : "=f"(r) : "f"(x));
    return r;
}

#define CP_COMMIT()  asm volatile("cp.async.commit_group;" ::: "memory")
#define CP_WAIT1()   asm volatile("cp.async.wait_group 1;" ::: "memory")
#define CP_WAIT0()   asm volatile("cp.async.wait_group 0;" ::: "memory")

#define LDSM_X4(r0,r1,r2,r3,addr) \
    asm volatile("ldmatrix.sync.aligned.m8n8.x4.shared.b16 {%0,%1,%2,%3}, [%4];" \
                 : "=r"(r0), "=r"(r1), "=r"(r2), "=r"(r3) : "r"(addr))

#define LDSM_X4A(r, addr) LDSM_X4((r)[0], (r)[1], (r)[2], (r)[3], addr)

// tf32 m16n8k8: a = 4 regs, b = 2 regs, fp32 accum
#define MMA16888(d, a, b0, b1) \
    asm volatile("mma.sync.aligned.m16n8k8.row.col.f32.tf32.tf32.f32 " \
                 "{%0,%1,%2,%3}, {%4,%5,%6,%7}, {%8,%9}, {%0,%1,%2,%3};" \
                 : "+f"((d)[0]), "+f"((d)[1]), "+f"((d)[2]), "+f"((d)[3]) \
                 : "r"((a)[0]), "r"((a)[1]), "r"((a)[2]), "r"((a)[3]), \
                   "r"(b0), "r"(b1))

// ============================================================
// TF32 GEMM: CTA 128x128, 4 warps (2x2 of 64x64), K-chunk 32 fp32,
// double-buffered cp.async + ldmatrix, SW128 swizzle.
// A: [M,K] fp32 RAW (rna applied in-register); B: [N,K] fp32 pre-rna'd.
// ============================================================
#define SM_A0   0
#define SM_B0   16384
#define SM_A1   32768
#define SM_B1   49152
#define GEMM_SMEM 65536

template<bool CHECK_M>
__device__ __forceinline__ void stage_chunk(uint32_t sb, uint32_t aoff, uint32_t boff,
                                            const char* ab, int ldAb,
                                            const char* bb, int ldBb,
                                            int bm, int M, int tid)
{
#pragma unroll
    for (int i = 0; i < 8; ++i) {
        int idx = tid + i * 128;
        int r = idx >> 3, seg = idx & 7;
        uint32_t d = sb + aoff + swz128((uint32_t)(r * 128 + seg * 16));
        const char* s = ab + (size_t)r * ldAb + seg * 16;
        int sz = (!CHECK_M || (bm + r) < M) ? 16 : 0;
        asm volatile("cp.async.cg.shared.global [%0], [%1], 16, %2;"
                     :: "r"(d), "l"(s), "r"(sz) : "memory");
    }
#pragma unroll
    for (int i = 0; i < 8; ++i) {
        int idx = tid + i * 128;
        int r = idx >> 3, seg = idx & 7;
        uint32_t d = sb + boff + swz128((uint32_t)(r * 128 + seg * 16));
        const char* s = bb + (size_t)r * ldBb + seg * 16;
        asm volatile("cp.async.cg.shared.global [%0], [%1], 16;"
                     :: "r"(d), "l"(s) : "memory");
    }
}

template<bool CHECK_M, bool BIAS>
__global__ __launch_bounds__(128, 2)
void tf32_gemm(const float* __restrict__ A, int ldA,
               const float* __restrict__ Bw, int ldB, int NC,
               const float* __restrict__ bias,
               float* __restrict__ C, int ldC, int M)
{
    extern __shared__ char smem_raw[];
    const uint32_t sb = (uint32_t)__cvta_generic_to_shared(smem_raw);
    const int tid  = threadIdx.x;
    const int lane = tid & 31;
    const int wid  = tid >> 5;
    const int wm   = wid & 1;
    const int wn   = wid >> 1;
    const int bm   = blockIdx.x * 128;
    const int bn   = blockIdx.y * 128;

    const int ldAb = ldA * 4;
    const int ldBb = ldB * 4;
    const char* Abase = (const char*)A + (size_t)bm * ldAb;
    const char* Bbase = (const char*)Bw + (size_t)bn * ldBb;

    float acc[4][8][4];
#pragma unroll
    for (int mt = 0; mt < 4; ++mt)
#pragma unroll
        for (int nb = 0; nb < 8; ++nb)
#pragma unroll
            for (int e = 0; e < 4; ++e) acc[mt][nb][e] = 0.f;

    const int a_row  = (lane & 7) + ((lane & 8) ? 8 : 0);
    const int a_colb = (lane & 16) ? 16 : 0;
    const int b_row  = (lane & 7) + ((lane & 16) ? 8 : 0);
    const int b_colb = (lane & 8) ? 16 : 0;

    stage_chunk<CHECK_M>(sb, SM_A0, SM_B0, Abase, ldAb, Bbase, ldBb, bm, M, tid);
    CP_COMMIT();

    for (int c = 0; c < NC; ++c) {
        const bool more = (c + 1) < NC;
        if (more) {
            const int cn = c + 1;
            const uint32_t aoff = (cn & 1) ? SM_A1 : SM_A0;
            const uint32_t boff = (cn & 1) ? SM_B1 : SM_B0;
            stage_chunk<CHECK_M>(sb, aoff, boff,
                                 Abase + (size_t)cn * 128, ldAb,
                                 Bbase + (size_t)cn * 128, ldBb, bm, M, tid);
            CP_COMMIT();
            CP_WAIT1();
        } else {
            CP_WAIT0();
        }
        __syncthreads();

        const uint32_t sA = sb + ((c & 1) ? SM_A1 : SM_A0);
        const uint32_t sB = sb + ((c & 1) ? SM_B1 : SM_B0);

#pragma unroll
        for (int kk = 0; kk < 4; ++kk) {
            const int kb = kk * 32;
            uint32_t afr[4][4];
#pragma unroll
            for (int mt = 0; mt < 4; ++mt) {
                uint32_t addr = sA + swz128((uint32_t)((wm * 64 + mt * 16 + a_row) * 128
                                                       + kb + a_colb));
                LDSM_X4A(afr[mt], addr);
#pragma unroll
                for (int j = 0; j < 4; ++j)
                    afr[mt][j] = __float_as_uint(tf32_rna(__uint_as_float(afr[mt][j])));
            }
            uint32_t bfr[4][4];
#pragma unroll
            for (int nb2 = 0; nb2 < 4; ++nb2) {
                uint32_t addr = sB + swz128((uint32_t)((wn * 64 + nb2 * 16 + b_row) * 128
                                                       + kb + b_colb));
                LDSM_X4A(bfr[nb2], addr);
            }
#pragma unroll
            for (int mt = 0; mt < 4; ++mt)
#pragma unroll
                for (int nb = 0; nb < 8; ++nb) {
                    const uint32_t b0 = bfr[nb >> 1][(nb & 1) * 2 + 0];
                    const uint32_t b1 = bfr[nb >> 1][(nb & 1) * 2 + 1];
                    MMA16888(acc[mt][nb], afr[mt], b0, b1);
                }
        }
        __syncthreads();
    }

    const int qr = lane >> 2;
    const int qc = (lane & 3) * 2;
#pragma unroll
    for (int mt = 0; mt < 4; ++mt) {
        const int row0 = bm + wm * 64 + mt * 16 + qr;
        const int row1 = row0 + 8;
        const bool ok0 = !CHECK_M || row0 < M;
        const bool ok1 = !CHECK_M || row1 < M;
#pragma unroll
        for (int nb = 0; nb < 8; ++nb) {
            const int col = bn + wn * 64 + nb * 8 + qc;
            float bx = 0.f, by = 0.f;
            if (BIAS) { bx = bias[col]; by = bias[col + 1]; }
            if (ok0) {
                float2 v = make_float2(acc[mt][nb][0] + bx, acc[mt][nb][1] + by);
                *(float2*)(C + (size_t)row0 * ldC + col) = v;
            }
            if (ok1) {
                float2 v = make_float2(acc[mt][nb][2] + bx, acc[mt][nb][3] + by);
                *(float2*)(C + (size_t)row1 * ldC + col) = v;
            }
        }
    }
}

// ============================================================
// Weight transpose + rna: fp32 W[K,N] -> fp32 W'[rowoff+n][k]
// ============================================================
__global__ void wtrans_kernel(const float* __restrict__ W, float* __restrict__ out,
                              int K, int N, int ldo, int rowoff)
{
    __shared__ float t[32][33];
    int k0 = blockIdx.x * 32, n0 = blockIdx.y * 32;
    int tx = threadIdx.x & 31, ty = threadIdx.x >> 5;
#pragma unroll
    for (int r = 0; r < 4; ++r)
        t[ty + r * 8][tx] = W[(size_t)(k0 + ty + r * 8) * N + n0 + tx];
    __syncthreads();
#pragma unroll
    for (int r = 0; r < 4; ++r) {
        int n = n0 + ty + r * 8;
        int k = k0 + tx;
        out[(size_t)(rowoff + n) * ldo + k] = tf32_rna(t[tx][ty + r * 8]);
    }
}

// ============================================================
// Boost
// ============================================================
__global__ void boost_kernel(const float* __restrict__ mask)
{
    __shared__ float red[128];
    float s = 0.f;
    for (int i = threadIdx.x; i < SS; i += 128) s += mask[i];
    red[threadIdx.x] = s;
    __syncthreads();
    for (int o = 64; o > 0; o >>= 1) {
        if (threadIdx.x < o) red[threadIdx.x] += red[threadIdx.x + o];
        __syncthreads();
    }
    if (threadIdx.x == 0) {
        float ratio = red[0] * (1.0f / (float)SS);
        float b = 1.0f;
        if (ratio > 1e-6f && ratio < 0.1f)
            b = fminf(1.0f + (0.1f - ratio) * 30.0f, 4.0f);
        g_boost = b;
    }
}

// ============================================================
// Tensor-core dual-branch attention.
// Block: one (b,h) x 128 q-rows. 256 threads = 8 warps x 16 q-rows.
// QK^T and P~V via tf32 m16n8k8; softmax in fragments; deferred norm.
// smem chunked layout: k-slabs of 32 fp32 = 128B rows, SW128 swizzle.
// ============================================================
#define ATT_SQ  0                          // Q: 2 chunks x (128 x 128B) = 32768
#define ATT_SK  32768                      // K: 2 chunks x ( 80 x 128B) = 20480
#define ATT_SP  53248                      // P: 3 chunks x (128 x 128B) = 49152
#define ATT_SV  102400                     // Vt:3 chunks x ( 64 x 128B) = 24576
#define ATT_SMEM_BYTES 126976

__global__ __launch_bounds__(256, 1)
void attn_kernel(const float* __restrict__ msk)
{
    extern __shared__ char smem_raw[];
    const uint32_t sb = (uint32_t)__cvta_generic_to_shared(smem_raw);
    const int tid  = threadIdx.x;
    const int lane = tid & 31;
    const int w    = tid >> 5;           // warp 0..7, rows [w*16, w*16+16)
    const int b    = blockIdx.y / NH;
    const int h    = blockIdx.y % NH;
    const int s0   = blockIdx.x * 128;

    const int a_row  = (lane & 7) + ((lane & 8) ? 8 : 0);
    const int a_colb = (lane & 16) ? 16 : 0;
    const int b_row  = (lane & 7) + ((lane & 16) ? 8 : 0);
    const int b_colb = (lane & 8) ? 16 : 0;

    // ---- zero P padding zone (t in [80,96), chunk 2 bytes 64..127) ----
#pragma unroll
    for (int i = 0; i < 8; ++i) {
        int idx = tid + i * 256;             // 2048
        int row = idx >> 4, c4 = idx & 15;
        uint32_t addr = sb + ATT_SP + 2 * 16384 + swz128((uint32_t)(row * 128 + 64 + c4 * 4));
        asm volatile("st.shared.f32 [%0], %1;" :: "r"(addr), "f"(0.f));
    }

    // ---- load Q tile [128 x 64], rna, chunked ----
    {
        const float* qb = g_Q + (size_t)(b * SS + s0) * DD + h * HDIM;
#pragma unroll
        for (int i = 0; i < 8; ++i) {
            int idx = tid + i * 256;         // 2048 float4
            int r  = idx >> 4;
            int d4 = (idx & 15) << 2;
            float4 v = *(const float4*)(qb + (size_t)r * DD + d4);
            v.x = tf32_rna(v.x); v.y = tf32_rna(v.y);
            v.z = tf32_rna(v.z); v.w = tf32_rna(v.w);
            uint32_t addr = sb + ATT_SQ + (d4 >> 5) * 16384
                          + swz128((uint32_t)(r * 128 + (d4 & 31) * 4));
            asm volatile("st.shared.v4.f32 [%0], {%1,%2,%3,%4};"
                         :: "r"(addr), "f"(v.x), "f"(v.y), "f"(v.z), "f"(v.w));
        }
    }

    float o1[8][4];
    const float boost = g_boost;

    for (int br = 0; br < 2; ++br) {
        const float* kb = g_KV + (size_t)(b * SKV) * KVLD + (br ? 2560 : 0) + h * HDIM;
        const float* vb = kb + 1280;

        // ---- K tile [80 keys x 64 d], rna, zero t>=77 ----
#pragma unroll
        for (int i = 0; i < 5; ++i) {
            int idx = tid + i * 256;         // 1280 float4
            int r  = idx >> 4;               // key 0..79
            int d4 = (idx & 15) << 2;
            float4 v = make_float4(0.f, 0.f, 0.f, 0.f);
            if (r < SKV) {
                v = *(const float4*)(kb + (size_t)r * KVLD + d4);
                v.x = tf32_rna(v.x); v.y = tf32_rna(v.y);
                v.z = tf32_rna(v.z); v.w = tf32_rna(v.w);
            }
            uint32_t addr = sb + ATT_SK + (d4 >> 5) * 10240
                          + swz128((uint32_t)(r * 128 + (d4 & 31) * 4));
            asm volatile("st.shared.v4.f32 [%0], {%1,%2,%3,%4};"
                         :: "r"(addr), "f"(v.x), "f"(v.y), "f"(v.z), "f"(v.w));
        }
        __syncthreads();   // Q+K ready

        // ---- scores: S[16 x 80] per warp ----
        float sfr[10][4];
#pragma unroll
        for (int n8 = 0; n8 < 10; ++n8)
#pragma unroll
            for (int e = 0; e < 4; ++e) sfr[n8][e] = 0.f;

#pragma unroll
        for (int kk = 0; kk < 8; ++kk) {
            const int ch = kk >> 2, kbb = (kk & 3) * 32;
            uint32_t af[4];
            LDSM_X4A(af, sb + ATT_SQ + ch * 16384
                         + swz128((uint32_t)((w * 16 + a_row) * 128 + kbb + a_colb)));
            uint32_t bf[5][4];
#pragma unroll
            for (int bt = 0; bt < 5; ++bt)
                LDSM_X4A(bf[bt], sb + ATT_SK + ch * 10240
                                 + swz128((uint32_t)((bt * 16 + b_row) * 128 + kbb + b_colb)));
#pragma unroll
            for (int n8 = 0; n8 < 10; ++n8)
                MMA16888(sfr[n8], af, bf[n8 >> 1][(n8 & 1) * 2], bf[n8 >> 1][(n8 & 1) * 2 + 1]);
        }

        // ---- softmax (rows split over 4 lanes), write P~ rna'd ----
        float invs[2];
#pragma unroll
        for (int hh = 0; hh < 2; ++hh) {
            float m = -INFINITY;
#pragma unroll
            for (int n8 = 0; n8 < 10; ++n8)
#pragma unroll
                for (int j = 0; j < 2; ++j) {
                    int col = n8 * 8 + (lane & 3) * 2 + j;
                    float v = sfr[n8][hh * 2 + j] * 0.125f;
                    if (col >= SKV) v = -INFINITY;
                    sfr[n8][hh * 2 + j] = v;
                    m = fmaxf(m, v);
                }
            m = fmaxf(m, __shfl_xor_sync(0xffffffffu, m, 1));
            m = fmaxf(m, __shfl_xor_sync(0xffffffffu, m, 2));
            float s = 0.f;
#pragma unroll
            for (int n8 = 0; n8 < 10; ++n8)
#pragma unroll
                for (int j = 0; j < 2; ++j) {
                    float e = __expf(sfr[n8][hh * 2 + j] - m);
                    sfr[n8][hh * 2 + j] = e;
                    s += e;
                }
            s += __shfl_xor_sync(0xffffffffu, s, 1);
            s += __shfl_xor_sync(0xffffffffu, s, 2);
            invs[hh] = 1.0f / s;

            const int row = w * 16 + (lane >> 2) + 8 * hh;
#pragma unroll
            for (int n8 = 0; n8 < 10; ++n8) {
                int t = n8 * 8 + (lane & 3) * 2;
                float e0 = tf32_rna(sfr[n8][hh * 2 + 0]);
                float e1 = tf32_rna(sfr[n8][hh * 2 + 1]);
                uint32_t addr = sb + ATT_SP + (t >> 5) * 16384
                              + swz128((uint32_t)(row * 128 + (t & 31) * 4));
                asm volatile("st.shared.v2.f32 [%0], {%1,%2};"
                             :: "r"(addr), "f"(e0), "f"(e1));
            }
        }

        // ---- Vt tile [64 d x 96 t] (transposed), rna, zero t>=77 ----
#pragma unroll
        for (int i = 0; i < 24; ++i) {
            int idx = tid + i * 256;         // 6144
            int d = idx & 63, t = idx >> 6;  // t 0..95
            float v = 0.f;
            if (t < SKV) v = tf32_rna(vb[(size_t)t * KVLD + d]);
            uint32_t addr = sb + ATT_SV + (t >> 5) * 8192
                          + swz128((uint32_t)(d * 128 + (t & 31) * 4));
            asm volatile("st.shared.f32 [%0], %1;" :: "r"(addr), "f"(v));
        }
        __syncthreads();   // P + V ready

        // ---- O = P~ @ V (deferred normalization) ----
        float of[8][4];
#pragma unroll
        for (int n8 = 0; n8 < 8; ++n8)
#pragma unroll
            for (int e = 0; e < 4; ++e) of[n8][e] = 0.f;

#pragma unroll
        for (int kk = 0; kk < 12; ++kk) {
            const int ch = kk >> 2, kbb = (kk & 3) * 32;
            uint32_t af[4];
            LDSM_X4A(af, sb + ATT_SP + ch * 16384
                         + swz128((uint32_t)((w * 16 + a_row) * 128 + kbb + a_colb)));
            uint32_t bf[4][4];
#pragma unroll
            for (int bt = 0; bt < 4; ++bt)
                LDSM_X4A(bf[bt], sb + ATT_SV + ch * 8192
                                 + swz128((uint32_t)((bt * 16 + b_row) * 128 + kbb + b_colb)));
#pragma unroll
            for (int n8 = 0; n8 < 8; ++n8)
                MMA16888(of[n8], af, bf[n8 >> 1][(n8 & 1) * 2], bf[n8 >> 1][(n8 & 1) * 2 + 1]);
        }

        // normalize
#pragma unroll
        for (int n8 = 0; n8 < 8; ++n8) {
            of[n8][0] *= invs[0]; of[n8][1] *= invs[0];
            of[n8][2] *= invs[1]; of[n8][3] *= invs[1];
        }

        if (br == 0) {
#pragma unroll
            for (int n8 = 0; n8 < 8; ++n8)
#pragma unroll
                for (int e = 0; e < 4; ++e) o1[n8][e] = of[n8][e];
            __syncthreads();   // protect Ks/Vs/Ps before branch-1 overwrites
        } else {
            const int row0 = w * 16 + (lane >> 2);
            const int row1 = row0 + 8;
            const float mb0 = msk[s0 + row0] * boost;
            const float mb1 = msk[s0 + row1] * boost;
            float* cb = g_comb + (size_t)(b * SS + s0) * DD + h * HDIM;
#pragma unroll
            for (int n8 = 0; n8 < 8; ++n8) {
                const int col = n8 * 8 + (lane & 3) * 2;
                float2 v0 = make_float2(o1[n8][0] + mb0 * of[n8][0],
                                        o1[n8][1] + mb0 * of[n8][1]);
                float2 v1 = make_float2(o1[n8][2] + mb1 * of[n8][2],
                                        o1[n8][3] + mb1 * of[n8][3]);
                *(float2*)(cb + (size_t)row0 * DD + col) = v0;
                *(float2*)(cb + (size_t)row1 * DD + col) = v1;
            }
        }
    }
}

// ============================================================
// launch
// ============================================================
extern "C" void kernel_launch(void* const* d_in, const int* in_sizes, int n_in,
                              void* d_out, int out_size)
{
    const float* hs   = (const float*)d_in[0];
    const float* ehs  = (const float*)d_in[1];
    const float* msk  = (const float*)d_in[2];
    const float* Wq   = (const float*)d_in[3];
    const float* Wk   = (const float*)d_in[4];
    const float* Wv   = (const float*)d_in[5];
    const float* Wkip = (const float*)d_in[6];
    const float* Wvip = (const float*)d_in[7];
    const float* Wo   = (const float*)d_in[8];
    const float* bo   = (const float*)d_in[9];
    float* out = (float*)d_out;

    float *gWt, *gWkvt, *gq, *gkv, *gc;
    cudaGetSymbolAddress((void**)&gWt,   g_Wt);
    cudaGetSymbolAddress((void**)&gWkvt, g_Wkvt);
    cudaGetSymbolAddress((void**)&gq,    g_Q);
    cudaGetSymbolAddress((void**)&gkv,   g_KV);
    cudaGetSymbolAddress((void**)&gc,    g_comb);

    cudaFuncSetAttribute(tf32_gemm<false, false>,
                         cudaFuncAttributeMaxDynamicSharedMemorySize, GEMM_SMEM);
    cudaFuncSetAttribute(tf32_gemm<true, false>,
                         cudaFuncAttributeMaxDynamicSharedMemorySize, GEMM_SMEM);
    cudaFuncSetAttribute(tf32_gemm<false, true>,
                         cudaFuncAttributeMaxDynamicSharedMemorySize, GEMM_SMEM);
    cudaFuncSetAttribute(attn_kernel,
                         cudaFuncAttributeMaxDynamicSharedMemorySize, ATT_SMEM_BYTES);

    // ---- Q projection (A = raw hs, rna in-GEMM) ----
    wtrans_kernel<<<dim3(DD / 32, DD / 32), 256>>>(Wq, gWt, DD, DD, DD, 0);
    tf32_gemm<false, false><<<dim3(MQ / 128, DD / 128), 128, GEMM_SMEM>>>(
        hs, DD, gWt, DD, DD / 32, nullptr, gq, DD, MQ);

    // ---- fused K/V/Kip/Vip projections (A = raw ehs) ----
    wtrans_kernel<<<dim3(CDIM / 32, DD / 32), 256>>>(Wk,   gWkvt, CDIM, DD, CDIM, 0);
    wtrans_kernel<<<dim3(CDIM / 32, DD / 32), 256>>>(Wv,   gWkvt, CDIM, DD, CDIM, 1280);
    wtrans_kernel<<<dim3(CDIM / 32, DD / 32), 256>>>(Wkip, gWkvt, CDIM, DD, CDIM, 2560);
    wtrans_kernel<<<dim3(CDIM / 32, DD / 32), 256>>>(Wvip, gWkvt, CDIM, DD, CDIM, 3840);
    tf32_gemm<true, false><<<dim3(3, KVLD / 128), 128, GEMM_SMEM>>>(
        ehs, CDIM, gWkvt, CDIM, CDIM / 32, nullptr, gkv, KVLD, MKV);

    // ---- boost + tensor-core attention ----
    boost_kernel<<<1, 128>>>(msk);
    attn_kernel<<<dim3(SS / 128, BB * NH), 256, ATT_SMEM_BYTES>>>(msk);

    // ---- output projection (+bias), A = raw g_comb ----
    wtrans_kernel<<<dim3(DD / 32, DD / 32), 256>>>(Wo, gWt, DD, DD, DD, 0);
    tf32_gemm<false, true><<<dim3(MQ / 128, DD / 128), 128, GEMM_SMEM>>>(
        gc, DD, gWt, DD, DD / 32, bo, out, DD, MQ);
}

// round 14
// speedup vs baseline: 10.0740x; 1.8658x over previous
#include <cuda_runtime.h>
#include <cuda_fp16.h>
#include <math.h>
#include <stdint.h>

// ---------------- problem constants ----------------
#define BB   4
#define SS   4096
#define DD   1280
#define SKV  77
#define CDIM 2048
#define NH   20
#define HDIM 64
#define MQ   (BB*SS)    // 16384
#define MKV  (BB*SKV)   // 308
#define KVLD 5120       // fused KV row: [K|V|Kip|Vip]

// ---------------- scratch ----------------
__device__ __half g_Ah   [(size_t)MQ * DD];        // fp16(hidden_states)
__device__ __half g_Aeh  [(size_t)MKV * CDIM];     // fp16(encoder_hidden_states)
__device__ __half g_Wth  [(size_t)DD * DD];        // fp16(W^T), Wq then Wo
__device__ __half g_Wkvth[(size_t)4 * DD * CDIM];  // fp16([Wk|Wv|Wkip|Wvip]^T)
__device__ __half g_Q    [(size_t)MQ * DD];        // fp16 Q
__device__ __half g_KV   [(size_t)MKV * KVLD];     // fp16 K/V/Kip/Vip
__device__ __half g_VT   [(size_t)BB * 2 * NH * 64 * 96]; // V^T per (b,br,h): [64 d][96 t], zero-init
__device__ __half g_comb [(size_t)MQ * DD];        // fp16 attention output
__device__ float  g_boost;

// ---------------- helpers ----------------
__device__ __forceinline__ uint32_t swz128(uint32_t b) { return b ^ ((b >> 3) & 0x70); }

#define CP_COMMIT()  asm volatile("cp.async.commit_group;" ::: "memory")
#define CP_WAIT1()   asm volatile("cp.async.wait_group 1;" ::: "memory")
#define CP_WAIT0()   asm volatile("cp.async.wait_group 0;" ::: "memory")

#define LDSM_X4(r0,r1,r2,r3,addr) \
    asm volatile("ldmatrix.sync.aligned.m8n8.x4.shared.b16 {%0,%1,%2,%3}, [%4];" \
                 : "=r"(r0), "=r"(r1), "=r"(r2), "=r"(r3) : "r"(addr))
#define LDSM_X4A(r, addr) LDSM_X4((r)[0], (r)[1], (r)[2], (r)[3], addr)

// fp16 m16n8k16, fp32 accum
#define MMAH(d, a, b0, b1) \
    asm volatile("mma.sync.aligned.m16n8k16.row.col.f32.f16.f16.f32 " \
                 "{%0,%1,%2,%3}, {%4,%5,%6,%7}, {%8,%9}, {%0,%1,%2,%3};" \
                 : "+f"((d)[0]), "+f"((d)[1]), "+f"((d)[2]), "+f"((d)[3]) \
                 : "r"((a)[0]), "r"((a)[1]), "r"((a)[2]), "r"((a)[3]), \
                   "r"(b0), "r"(b1))

// ============================================================
// FP16 GEMM: CTA 128x128, 4 warps (2x2 of 64x64), K-chunk 64 fp16 (128B),
// double-buffered cp.async + ldmatrix, SW128 swizzle. Geometry == proven R7.
//   A: [M,K] fp16 row-major; B: [N,K] fp16 K-major.
//   OUTH: fp16 output; VT: also scatter V/Vip cols transposed into g_VT.
// ============================================================
#define SM_A0   0
#define SM_B0   16384
#define SM_A1   32768
#define SM_B1   49152
#define GEMM_SMEM 65536

template<bool CHECK_M>
__device__ __forceinline__ void stage_chunk(uint32_t sb, uint32_t aoff, uint32_t boff,
                                            const char* ab, int ldAb,
                                            const char* bb, int ldBb,
                                            int bm, int M, int tid)
{
#pragma unroll
    for (int i = 0; i < 8; ++i) {
        int idx = tid + i * 128;
        int r = idx >> 3, seg = idx & 7;
        uint32_t d = sb + aoff + swz128((uint32_t)(r * 128 + seg * 16));
        const char* s = ab + (size_t)r * ldAb + seg * 16;
        int sz = (!CHECK_M || (bm + r) < M) ? 16 : 0;
        asm volatile("cp.async.cg.shared.global [%0], [%1], 16, %2;"
                     :: "r"(d), "l"(s), "r"(sz) : "memory");
    }
#pragma unroll
    for (int i = 0; i < 8; ++i) {
        int idx = tid + i * 128;
        int r = idx >> 3, seg = idx & 7;
        uint32_t d = sb + boff + swz128((uint32_t)(r * 128 + seg * 16));
        const char* s = bb + (size_t)r * ldBb + seg * 16;
        asm volatile("cp.async.cg.shared.global [%0], [%1], 16;"
                     :: "r"(d), "l"(s) : "memory");
    }
}

template<bool CHECK_M, bool BIAS, bool OUTH, bool VT>
__global__ __launch_bounds__(128, 2)
void h_gemm(const __half* __restrict__ A, int ldA,
            const __half* __restrict__ Bw, int ldB, int NC,
            const float* __restrict__ bias,
            void* __restrict__ Cv, int ldC, int M)
{
    extern __shared__ char smem_raw[];
    const uint32_t sb = (uint32_t)__cvta_generic_to_shared(smem_raw);
    const int tid  = threadIdx.x;
    const int lane = tid & 31;
    const int wid  = tid >> 5;
    const int wm   = wid & 1;
    const int wn   = wid >> 1;
    const int bm   = blockIdx.x * 128;
    const int bn   = blockIdx.y * 128;

    const int ldAb = ldA * 2;
    const int ldBb = ldB * 2;
    const char* Abase = (const char*)A + (size_t)bm * ldAb;
    const char* Bbase = (const char*)Bw + (size_t)bn * ldBb;

    float acc[4][8][4];
#pragma unroll
    for (int mt = 0; mt < 4; ++mt)
#pragma unroll
        for (int nb = 0; nb < 8; ++nb)
#pragma unroll
            for (int e = 0; e < 4; ++e) acc[mt][nb][e] = 0.f;

    const int a_row  = (lane & 7) + ((lane & 8) ? 8 : 0);
    const int a_colb = (lane & 16) ? 16 : 0;
    const int b_row  = (lane & 7) + ((lane & 16) ? 8 : 0);
    const int b_colb = (lane & 8) ? 16 : 0;

    stage_chunk<CHECK_M>(sb, SM_A0, SM_B0, Abase, ldAb, Bbase, ldBb, bm, M, tid);
    CP_COMMIT();

    for (int c = 0; c < NC; ++c) {
        const bool more = (c + 1) < NC;
        if (more) {
            const int cn = c + 1;
            const uint32_t aoff = (cn & 1) ? SM_A1 : SM_A0;
            const uint32_t boff = (cn & 1) ? SM_B1 : SM_B0;
            stage_chunk<CHECK_M>(sb, aoff, boff,
                                 Abase + (size_t)cn * 128, ldAb,
                                 Bbase + (size_t)cn * 128, ldBb, bm, M, tid);
            CP_COMMIT();
            CP_WAIT1();
        } else {
            CP_WAIT0();
        }
        __syncthreads();

        const uint32_t sA = sb + ((c & 1) ? SM_A1 : SM_A0);
        const uint32_t sB = sb + ((c & 1) ? SM_B1 : SM_B0);

#pragma unroll
        for (int kk = 0; kk < 4; ++kk) {      // 4 x k16 (32B each)
            const int kb = kk * 32;
            uint32_t afr[4][4];
#pragma unroll
            for (int mt = 0; mt < 4; ++mt)
                LDSM_X4A(afr[mt], sA + swz128((uint32_t)((wm * 64 + mt * 16 + a_row) * 128
                                                         + kb + a_colb)));
            uint32_t bfr[4][4];
#pragma unroll
            for (int nb2 = 0; nb2 < 4; ++nb2)
                LDSM_X4A(bfr[nb2], sB + swz128((uint32_t)((wn * 64 + nb2 * 16 + b_row) * 128
                                                          + kb + b_colb)));
#pragma unroll
            for (int mt = 0; mt < 4; ++mt)
#pragma unroll
                for (int nb = 0; nb < 8; ++nb)
                    MMAH(acc[mt][nb], afr[mt],
                         bfr[nb >> 1][(nb & 1) * 2], bfr[nb >> 1][(nb & 1) * 2 + 1]);
        }
        __syncthreads();
    }

    const int qr = lane >> 2;
    const int qc = (lane & 3) * 2;
#pragma unroll
    for (int mt = 0; mt < 4; ++mt) {
        const int row0 = bm + wm * 64 + mt * 16 + qr;
        const int row1 = row0 + 8;
        const bool ok0 = !CHECK_M || row0 < M;
        const bool ok1 = !CHECK_M || row1 < M;
#pragma unroll
        for (int nb = 0; nb < 8; ++nb) {
            const int col = bn + wn * 64 + nb * 8 + qc;
            float bx = 0.f, by = 0.f;
            if (BIAS) { bx = bias[col]; by = bias[col + 1]; }
            float c00 = acc[mt][nb][0] + bx, c01 = acc[mt][nb][1] + by;
            float c10 = acc[mt][nb][2] + bx, c11 = acc[mt][nb][3] + by;
            if (OUTH) {
                __half* C = (__half*)Cv;
                if (ok0) *(__half2*)(C + (size_t)row0 * ldC + col) = __floats2half2_rn(c00, c01);
                if (ok1) *(__half2*)(C + (size_t)row1 * ldC + col) = __floats2half2_rn(c10, c11);
            } else {
                float* C = (float*)Cv;
                if (ok0) *(float2*)(C + (size_t)row0 * ldC + col) = make_float2(c00, c01);
                if (ok1) *(float2*)(C + (size_t)row1 * ldC + col) = make_float2(c10, c11);
            }
            if (VT) {
                int sec = col / 1280;
                if (sec & 1) {                 // V or Vip section
                    int brch = sec >> 1;
                    int within = col - sec * 1280;
                    int hh = within >> 6, d = within & 63;
                    if (ok0) {
                        int bb = row0 / 77, t = row0 - bb * 77;
                        size_t base = ((((size_t)bb * 2 + brch) * NH + hh) * 64 + d) * 96 + t;
                        g_VT[base]      = __float2half(c00);
                        g_VT[base + 96] = __float2half(c01);
                    }
                    if (ok1) {
                        int bb = row1 / 77, t = row1 - bb * 77;
                        size_t base = ((((size_t)bb * 2 + brch) * NH + hh) * 64 + d) * 96 + t;
                        g_VT[base]      = __float2half(c10);
                        g_VT[base + 96] = __float2half(c11);
                    }
                }
            }
        }
    }
}

// ============================================================
// fp32 -> fp16 elementwise convert
// ============================================================
__global__ void hconv_kernel(const float* __restrict__ X, __half* __restrict__ out)
{
    int i4 = (blockIdx.x * 256 + threadIdx.x) * 4;
    float4 v = *(const float4*)(X + i4);
    __half2 a = __floats2half2_rn(v.x, v.y);
    __half2 b = __floats2half2_rn(v.z, v.w);
    uint2 p;
    p.x = *(uint32_t*)&a;
    p.y = *(uint32_t*)&b;
    *(uint2*)(out + i4) = p;
}

// ============================================================
// Weight transpose -> fp16: W[K,N] fp32 -> W'[rowoff+n][k] fp16
// ============================================================
__global__ void wtrans_kernel(const float* __restrict__ W, __half* __restrict__ out,
                              int K, int N, int ldo, int rowoff)
{
    __shared__ float t[32][33];
    int k0 = blockIdx.x * 32, n0 = blockIdx.y * 32;
    int tx = threadIdx.x & 31, ty = threadIdx.x >> 5;
#pragma unroll
    for (int r = 0; r < 4; ++r)
        t[ty + r * 8][tx] = W[(size_t)(k0 + ty + r * 8) * N + n0 + tx];
    __syncthreads();
#pragma unroll
    for (int r = 0; r < 4; ++r) {
        int n = n0 + ty + r * 8;
        int k = k0 + tx;
        out[(size_t)(rowoff + n) * ldo + k] = __float2half(t[tx][ty + r * 8]);
    }
}

// ============================================================
// Boost
// ============================================================
__global__ void boost_kernel(const float* __restrict__ mask)
{
    __shared__ float red[128];
    float s = 0.f;
    for (int i = threadIdx.x; i < SS; i += 128) s += mask[i];
    red[threadIdx.x] = s;
    __syncthreads();
    for (int o = 64; o > 0; o >>= 1) {
        if (threadIdx.x < o) red[threadIdx.x] += red[threadIdx.x + o];
        __syncthreads();
    }
    if (threadIdx.x == 0) {
        float ratio = red[0] * (1.0f / (float)SS);
        float b = 1.0f;
        if (ratio > 1e-6f && ratio < 0.1f)
            b = fminf(1.0f + (0.1f - ratio) * 30.0f, 4.0f);
        g_boost = b;
    }
}

// ============================================================
// FP16 tensor-core dual-branch attention.
// Block: (b,h) x 128 q-rows; 8 warps x 16 rows. All staging via cp.async.
// Q [128x64]h, K [80x64]h, P [128x96]h (2 t-chunks), V^T [64x96]h (2 t-chunks).
// ============================================================
#define ATT_SQ  0          // 16384
#define ATT_SK  16384      // 10240
#define ATT_SP  26624      // 32768 (2 x 128 x 128B)
#define ATT_SV  59392      // 16384 (2 x  64 x 128B)
#define ATT_SMEM_BYTES 75776

__global__ __launch_bounds__(256, 2)
void attn_kernel(const float* __restrict__ msk)
{
    extern __shared__ char smem_raw[];
    const uint32_t sb = (uint32_t)__cvta_generic_to_shared(smem_raw);
    const int tid  = threadIdx.x;
    const int lane = tid & 31;
    const int w    = tid >> 5;
    const int b    = blockIdx.y / NH;
    const int h    = blockIdx.y % NH;
    const int s0   = blockIdx.x * 128;

    const int a_row  = (lane & 7) + ((lane & 8) ? 8 : 0);
    const int a_colb = (lane & 16) ? 16 : 0;
    const int b_row  = (lane & 7) + ((lane & 16) ? 8 : 0);
    const int b_colb = (lane & 8) ? 16 : 0;

    // pre-zero P chunk1 bytes [32,64) (t 80..95) — written once, persists
#pragma unroll
    for (int i = 0; i < 4; ++i) {
        int idx = tid + i * 256;             // 1024
        int row = idx >> 3, c = idx & 7;
        uint32_t addr = sb + ATT_SP + 16384 + swz128((uint32_t)(row * 128 + 32 + c * 4));
        asm volatile("st.shared.f32 [%0], %1;" :: "r"(addr), "f"(0.f));
    }

    // stage Q via cp.async (joins branch-0 commit group)
    {
        const char* qh = (const char*)(g_Q + (size_t)(b * SS + s0) * DD + h * HDIM);
#pragma unroll
        for (int i = 0; i < 4; ++i) {
            int idx = tid + i * 256;         // 1024
            int r = idx >> 3, seg = idx & 7;
            uint32_t d = sb + ATT_SQ + swz128((uint32_t)(r * 128 + seg * 16));
            const char* s = qh + (size_t)r * (DD * 2) + seg * 16;
            asm volatile("cp.async.cg.shared.global [%0], [%1], 16;"
                         :: "r"(d), "l"(s) : "memory");
        }
    }

    float o1[8][4];
    const float boost = g_boost;

    for (int br = 0; br < 2; ++br) {
        const char* kb = (const char*)(g_KV + (size_t)(b * SKV) * KVLD + br * 2560 + h * HDIM);
        const char* vt = (const char*)(g_VT + ((((size_t)b * 2 + br) * NH + h) * 64) * 96);

        // K: 80 rows x 8 segs (rows >= 77 zero-filled)
#pragma unroll
        for (int i = 0; i < 3; ++i) {
            int idx = tid + i * 256;
            if (idx < 640) {
                int r = idx >> 3, seg = idx & 7;
                uint32_t d = sb + ATT_SK + swz128((uint32_t)(r * 128 + seg * 16));
                const char* s = kb + (size_t)r * (KVLD * 2) + seg * 16;
                int sz = (r < SKV) ? 16 : 0;
                asm volatile("cp.async.cg.shared.global [%0], [%1], 16, %2;"
                             :: "r"(d), "l"(s), "r"(sz) : "memory");
            }
        }
        // V^T: 64 rows x 12 segs (sg 0..7 -> chunk0 t0-63; 8..11 -> chunk1 t64-95)
#pragma unroll
        for (int i = 0; i < 4; ++i) {
            int idx = tid + i * 256;         // 1024, use 12/16
            int r = idx >> 4, sg = idx & 15;
            if (sg < 12) {
                int ch = sg >> 3, s2 = sg & 7;
                uint32_t d = sb + ATT_SV + ch * 8192 + swz128((uint32_t)(r * 128 + s2 * 16));
                const char* s = vt + (size_t)r * 192 + sg * 16;
                asm volatile("cp.async.cg.shared.global [%0], [%1], 16;"
                             :: "r"(d), "l"(s) : "memory");
            }
        }
        CP_COMMIT();
        CP_WAIT0();
        __syncthreads();

        // ---- scores: S[16 x 80] per warp (k = 64, 4 x k16) ----
        float sfr[10][4];
#pragma unroll
        for (int n8 = 0; n8 < 10; ++n8)
#pragma unroll
            for (int e = 0; e < 4; ++e) sfr[n8][e] = 0.f;

#pragma unroll
        for (int kk = 0; kk < 4; ++kk) {
            const int kbb = kk * 32;
            uint32_t af[4];
            LDSM_X4A(af, sb + ATT_SQ + swz128((uint32_t)((w * 16 + a_row) * 128 + kbb + a_colb)));
            uint32_t bf[5][4];
#pragma unroll
            for (int bt = 0; bt < 5; ++bt)
                LDSM_X4A(bf[bt], sb + ATT_SK
                                 + swz128((uint32_t)((bt * 16 + b_row) * 128 + kbb + b_colb)));
#pragma unroll
            for (int n8 = 0; n8 < 10; ++n8)
                MMAH(sfr[n8], af, bf[n8 >> 1][(n8 & 1) * 2], bf[n8 >> 1][(n8 & 1) * 2 + 1]);
        }

        // ---- softmax, write P~ fp16 ----
        float invs[2];
#pragma unroll
        for (int hh = 0; hh < 2; ++hh) {
            float m = -INFINITY;
#pragma unroll
            for (int n8 = 0; n8 < 10; ++n8)
#pragma unroll
                for (int j = 0; j < 2; ++j) {
                    int col = n8 * 8 + (lane & 3) * 2 + j;
                    float v = sfr[n8][hh * 2 + j] * 0.125f;
                    if (col >= SKV) v = -INFINITY;
                    sfr[n8][hh * 2 + j] = v;
                    m = fmaxf(m, v);
                }
            m = fmaxf(m, __shfl_xor_sync(0xffffffffu, m, 1));
            m = fmaxf(m, __shfl_xor_sync(0xffffffffu, m, 2));
            float s = 0.f;
#pragma unroll
            for (int n8 = 0; n8 < 10; ++n8)
#pragma unroll
                for (int j = 0; j < 2; ++j) {
                    float e = __expf(sfr[n8][hh * 2 + j] - m);
                    sfr[n8][hh * 2 + j] = e;
                    s += e;
                }
            s += __shfl_xor_sync(0xffffffffu, s, 1);
            s += __shfl_xor_sync(0xffffffffu, s, 2);
            invs[hh] = 1.0f / s;

            const int row = w * 16 + (lane >> 2) + 8 * hh;
#pragma unroll
            for (int n8 = 0; n8 < 10; ++n8) {
                int t = n8 * 8 + (lane & 3) * 2;
                __half2 hp = __floats2half2_rn(sfr[n8][hh * 2 + 0], sfr[n8][hh * 2 + 1]);
                uint32_t hv = *(uint32_t*)&hp;
                uint32_t addr = sb + ATT_SP + (t >> 6) * 16384
                              + swz128((uint32_t)(row * 128 + (t & 63) * 2));
                asm volatile("st.shared.b32 [%0], %1;" :: "r"(addr), "r"(hv));
            }
        }
        __syncthreads();   // P visible (V already staged)

        // ---- O = P~ @ V (k = 96, 6 x k16, deferred norm) ----
        float of[8][4];
#pragma unroll
        for (int n8 = 0; n8 < 8; ++n8)
#pragma unroll
            for (int e = 0; e < 4; ++e) of[n8][e] = 0.f;

#pragma unroll
        for (int kk = 0; kk < 6; ++kk) {
            const int ch = kk >> 2, kbb = (kk & 3) * 32;
            uint32_t af[4];
            LDSM_X4A(af, sb + ATT_SP + ch * 16384
                         + swz128((uint32_t)((w * 16 + a_row) * 128 + kbb + a_colb)));
            uint32_t bf[4][4];
#pragma unroll
            for (int bt = 0; bt < 4; ++bt)
                LDSM_X4A(bf[bt], sb + ATT_SV + ch * 8192
                                 + swz128((uint32_t)((bt * 16 + b_row) * 128 + kbb + b_colb)));
#pragma unroll
            for (int n8 = 0; n8 < 8; ++n8)
                MMAH(of[n8], af, bf[n8 >> 1][(n8 & 1) * 2], bf[n8 >> 1][(n8 & 1) * 2 + 1]);
        }

#pragma unroll
        for (int n8 = 0; n8 < 8; ++n8) {
            of[n8][0] *= invs[0]; of[n8][1] *= invs[0];
            of[n8][2] *= invs[1]; of[n8][3] *= invs[1];
        }

        if (br == 0) {
#pragma unroll
            for (int n8 = 0; n8 < 8; ++n8)
#pragma unroll
                for (int e = 0; e < 4; ++e) o1[n8][e] = of[n8][e];
            __syncthreads();   // all PV reads done before branch-1 restages
        } else {
            const int row0 = w * 16 + (lane >> 2);
            const int row1 = row0 + 8;
            const float mb0 = msk[s0 + row0] * boost;
            const float mb1 = msk[s0 + row1] * boost;
            __half* cb = g_comb + (size_t)(b * SS + s0) * DD + h * HDIM;
#pragma unroll
            for (int n8 = 0; n8 < 8; ++n8) {
                const int col = n8 * 8 + (lane & 3) * 2;
                *(__half2*)(cb + (size_t)row0 * DD + col) =
                    __floats2half2_rn(o1[n8][0] + mb0 * of[n8][0],
                                      o1[n8][1] + mb0 * of[n8][1]);
                *(__half2*)(cb + (size_t)row1 * DD + col) =
                    __floats2half2_rn(o1[n8][2] + mb1 * of[n8][2],
                                      o1[n8][3] + mb1 * of[n8][3]);
            }
        }
    }
}

// ============================================================
// launch
// ============================================================
extern "C" void kernel_launch(void* const* d_in, const int* in_sizes, int n_in,
                              void* d_out, int out_size)
{
    const float* hs   = (const float*)d_in[0];
    const float* ehs  = (const float*)d_in[1];
    const float* msk  = (const float*)d_in[2];
    const float* Wq   = (const float*)d_in[3];
    const float* Wk   = (const float*)d_in[4];
    const float* Wv   = (const float*)d_in[5];
    const float* Wkip = (const float*)d_in[6];
    const float* Wvip = (const float*)d_in[7];
    const float* Wo   = (const float*)d_in[8];
    const float* bo   = (const float*)d_in[9];
    float* out = (float*)d_out;

    __half *gAh, *gAeh, *gWth, *gWkvth, *gq, *gkv, *gc;
    cudaGetSymbolAddress((void**)&gAh,    g_Ah);
    cudaGetSymbolAddress((void**)&gAeh,   g_Aeh);
    cudaGetSymbolAddress((void**)&gWth,   g_Wth);
    cudaGetSymbolAddress((void**)&gWkvth, g_Wkvth);
    cudaGetSymbolAddress((void**)&gq,     g_Q);
    cudaGetSymbolAddress((void**)&gkv,    g_KV);
    cudaGetSymbolAddress((void**)&gc,     g_comb);

    cudaFuncSetAttribute((h_gemm<false, false, true,  false>),
                         cudaFuncAttributeMaxDynamicSharedMemorySize, GEMM_SMEM);
    cudaFuncSetAttribute((h_gemm<true,  false, true,  true>),
                         cudaFuncAttributeMaxDynamicSharedMemorySize, GEMM_SMEM);
    cudaFuncSetAttribute((h_gemm<false, true,  false, false>),
                         cudaFuncAttributeMaxDynamicSharedMemorySize, GEMM_SMEM);
    cudaFuncSetAttribute(attn_kernel,
                         cudaFuncAttributeMaxDynamicSharedMemorySize, ATT_SMEM_BYTES);

    // ---- Q projection: fp16 convert + GEMM (fp16 out) ----
    hconv_kernel<<<(MQ * DD) / 1024, 256>>>(hs, gAh);
    wtrans_kernel<<<dim3(DD / 32, DD / 32), 256>>>(Wq, gWth, DD, DD, DD, 0);
    h_gemm<false, false, true, false><<<dim3(MQ / 128, DD / 128), 128, GEMM_SMEM>>>(
        gAh, DD, gWth, DD, DD / 64, nullptr, gq, DD, MQ);

    // ---- fused K/V/Kip/Vip projections (fp16 out + V^T scatter) ----
    hconv_kernel<<<(MKV * CDIM) / 1024, 256>>>(ehs, gAeh);
    wtrans_kernel<<<dim3(CDIM / 32, DD / 32), 256>>>(Wk,   gWkvth, CDIM, DD, CDIM, 0);
    wtrans_kernel<<<dim3(CDIM / 32, DD / 32), 256>>>(Wv,   gWkvth, CDIM, DD, CDIM, 1280);
    wtrans_kernel<<<dim3(CDIM / 32, DD / 32), 256>>>(Wkip, gWkvth, CDIM, DD, CDIM, 2560);
    wtrans_kernel<<<dim3(CDIM / 32, DD / 32), 256>>>(Wvip, gWkvth, CDIM, DD, CDIM, 3840);
    h_gemm<true, false, true, true><<<dim3(3, KVLD / 128), 128, GEMM_SMEM>>>(
        gAeh, CDIM, gWkvth, CDIM, CDIM / 64, nullptr, gkv, KVLD, MKV);

    // ---- boost + fp16 tensor-core attention (writes fp16 g_comb) ----
    boost_kernel<<<1, 128>>>(msk);
    attn_kernel<<<dim3(SS / 128, BB * NH), 256, ATT_SMEM_BYTES>>>(msk);

    // ---- output projection (+bias), fp32 out ----
    wtrans_kernel<<<dim3(DD / 32, DD / 32), 256>>>(Wo, gWth, DD, DD, DD, 0);
    h_gemm<false, true, false, false><<<dim3(MQ / 128, DD / 128), 128, GEMM_SMEM>>>(
        gc, DD, gWth, DD, DD / 64, bo, out, DD, MQ);
}

// round 15
// speedup vs baseline: 10.3729x; 1.0297x over previous
#include <cuda_runtime.h>
#include <cuda_fp16.h>
#include <math.h>
#include <stdint.h>

// ---------------- problem constants ----------------
#define BB   4
#define SS   4096
#define DD   1280
#define SKV  77
#define CDIM 2048
#define NH   20
#define HDIM 64
#define MQ   (BB*SS)    // 16384
#define MKV  (BB*SKV)   // 308
#define KVLD 5120       // fused KV row: [K|V|Kip|Vip]

// ---------------- scratch ----------------
__device__ __half g_Ah   [(size_t)MQ * DD];        // fp16(hidden_states)
__device__ __half g_Aeh  [(size_t)MKV * CDIM];     // fp16(encoder_hidden_states)
__device__ __half g_Wth  [(size_t)DD * DD];        // fp16(Wq^T)
__device__ __half g_Wth2 [(size_t)DD * DD];        // fp16(Wo^T)
__device__ __half g_Wkvth[(size_t)4 * DD * CDIM];  // fp16([Wk|Wv|Wkip|Wvip]^T)
__device__ __half g_Q    [(size_t)MQ * DD];        // fp16 Q
__device__ __half g_KV   [(size_t)MKV * KVLD];     // fp16 K/V/Kip/Vip
__device__ __half g_VT   [(size_t)BB * 2 * NH * 64 * 96]; // V^T per (b,br,h), zero-init
__device__ __half g_comb [(size_t)MQ * DD];        // fp16 attention output
__device__ float  g_boost;

// ---------------- helpers ----------------
__device__ __forceinline__ uint32_t swz128(uint32_t b) { return b ^ ((b >> 3) & 0x70); }

#define CP_COMMIT()  asm volatile("cp.async.commit_group;" ::: "memory")
#define CP_WAIT1()   asm volatile("cp.async.wait_group 1;" ::: "memory")
#define CP_WAIT0()   asm volatile("cp.async.wait_group 0;" ::: "memory")

#define LDSM_X4(r0,r1,r2,r3,addr) \
    asm volatile("ldmatrix.sync.aligned.m8n8.x4.shared.b16 {%0,%1,%2,%3}, [%4];" \
                 : "=r"(r0), "=r"(r1), "=r"(r2), "=r"(r3) : "r"(addr))
#define LDSM_X4A(r, addr) LDSM_X4((r)[0], (r)[1], (r)[2], (r)[3], addr)

// fp16 m16n8k16, fp32 accum
#define MMAH(d, a, b0, b1) \
    asm volatile("mma.sync.aligned.m16n8k16.row.col.f32.f16.f16.f32 " \
                 "{%0,%1,%2,%3}, {%4,%5,%6,%7}, {%8,%9}, {%0,%1,%2,%3};" \
                 : "+f"((d)[0]), "+f"((d)[1]), "+f"((d)[2]), "+f"((d)[3]) \
                 : "r"((a)[0]), "r"((a)[1]), "r"((a)[2]), "r"((a)[3]), \
                   "r"(b0), "r"(b1))

// ============================================================
// FP16 GEMM: CTA 128x128, 4 warps (2x2 of 64x64), K-chunk 64 fp16 (128B),
// THREE-stage cp.async pipeline (one __syncthreads per chunk), SW128 swizzle.
//   A: [M,K] fp16 row-major; B: [N,K] fp16 K-major.
// ============================================================
#define GSTG      32768             // per-stage bytes (16K A + 16K B)
#define GEMM_SMEM (3 * GSTG)        // 98304

template<bool CHECK_M>
__device__ __forceinline__ void stage_chunk(uint32_t sb, int stg,
                                            const char* ab, int ldAb,
                                            const char* bb, int ldBb,
                                            int bm, int M, int tid)
{
    const uint32_t aoff = (uint32_t)stg * GSTG;
    const uint32_t boff = aoff + 16384;
#pragma unroll
    for (int i = 0; i < 8; ++i) {
        int idx = tid + i * 128;
        int r = idx >> 3, seg = idx & 7;
        uint32_t d = sb + aoff + swz128((uint32_t)(r * 128 + seg * 16));
        const char* s = ab + (size_t)r * ldAb + seg * 16;
        int sz = (!CHECK_M || (bm + r) < M) ? 16 : 0;
        asm volatile("cp.async.cg.shared.global [%0], [%1], 16, %2;"
                     :: "r"(d), "l"(s), "r"(sz) : "memory");
    }
#pragma unroll
    for (int i = 0; i < 8; ++i) {
        int idx = tid + i * 128;
        int r = idx >> 3, seg = idx & 7;
        uint32_t d = sb + boff + swz128((uint32_t)(r * 128 + seg * 16));
        const char* s = bb + (size_t)r * ldBb + seg * 16;
        asm volatile("cp.async.cg.shared.global [%0], [%1], 16;"
                     :: "r"(d), "l"(s) : "memory");
    }
}

template<bool CHECK_M, bool BIAS, bool OUTH, bool VT>
__global__ __launch_bounds__(128, 2)
void h_gemm(const __half* __restrict__ A, int ldA,
            const __half* __restrict__ Bw, int ldB, int NC,
            const float* __restrict__ bias,
            void* __restrict__ Cv, int ldC, int M)
{
    extern __shared__ char smem_raw[];
    const uint32_t sb = (uint32_t)__cvta_generic_to_shared(smem_raw);
    const int tid  = threadIdx.x;
    const int lane = tid & 31;
    const int wid  = tid >> 5;
    const int wm   = wid & 1;
    const int wn   = wid >> 1;
    const int bm   = blockIdx.x * 128;
    const int bn   = blockIdx.y * 128;

    const int ldAb = ldA * 2;
    const int ldBb = ldB * 2;
    const char* Abase = (const char*)A + (size_t)bm * ldAb;
    const char* Bbase = (const char*)Bw + (size_t)bn * ldBb;

    float acc[4][8][4];
#pragma unroll
    for (int mt = 0; mt < 4; ++mt)
#pragma unroll
        for (int nb = 0; nb < 8; ++nb)
#pragma unroll
            for (int e = 0; e < 4; ++e) acc[mt][nb][e] = 0.f;

    const int a_row  = (lane & 7) + ((lane & 8) ? 8 : 0);
    const int a_colb = (lane & 16) ? 16 : 0;
    const int b_row  = (lane & 7) + ((lane & 16) ? 8 : 0);
    const int b_colb = (lane & 8) ? 16 : 0;

    // prologue: stage chunks 0,1 into stages 0,1
    stage_chunk<CHECK_M>(sb, 0, Abase, ldAb, Bbase, ldBb, bm, M, tid);
    CP_COMMIT();
    stage_chunk<CHECK_M>(sb, 1, Abase + 128, ldAb, Bbase + 128, ldBb, bm, M, tid);
    CP_COMMIT();

    int s = 0;                      // stage index = c % 3
    for (int c = 0; c < NC; ++c) {
        if (c + 1 < NC) CP_WAIT1(); else CP_WAIT0();
        __syncthreads();            // chunk c visible; prior compute done (WAR fence)
        if (c + 2 < NC) {
            int s2 = s + 2; if (s2 >= 3) s2 -= 3;
            stage_chunk<CHECK_M>(sb, s2,
                                 Abase + (size_t)(c + 2) * 128, ldAb,
                                 Bbase + (size_t)(c + 2) * 128, ldBb, bm, M, tid);
            CP_COMMIT();
        }

        const uint32_t sA = sb + (uint32_t)s * GSTG;
        const uint32_t sB = sA + 16384;

#pragma unroll
        for (int kk = 0; kk < 4; ++kk) {      // 4 x k16 (32B each)
            const int kb = kk * 32;
            uint32_t afr[4][4];
#pragma unroll
            for (int mt = 0; mt < 4; ++mt)
                LDSM_X4A(afr[mt], sA + swz128((uint32_t)((wm * 64 + mt * 16 + a_row) * 128
                                                         + kb + a_colb)));
            uint32_t bfr[4][4];
#pragma unroll
            for (int nb2 = 0; nb2 < 4; ++nb2)
                LDSM_X4A(bfr[nb2], sB + swz128((uint32_t)((wn * 64 + nb2 * 16 + b_row) * 128
                                                          + kb + b_colb)));
#pragma unroll
            for (int mt = 0; mt < 4; ++mt)
#pragma unroll
                for (int nb = 0; nb < 8; ++nb)
                    MMAH(acc[mt][nb], afr[mt],
                         bfr[nb >> 1][(nb & 1) * 2], bfr[nb >> 1][(nb & 1) * 2 + 1]);
        }
        if (++s == 3) s = 0;
    }

    const int qr = lane >> 2;
    const int qc = (lane & 3) * 2;
#pragma unroll
    for (int mt = 0; mt < 4; ++mt) {
        const int row0 = bm + wm * 64 + mt * 16 + qr;
        const int row1 = row0 + 8;
        const bool ok0 = !CHECK_M || row0 < M;
        const bool ok1 = !CHECK_M || row1 < M;
#pragma unroll
        for (int nb = 0; nb < 8; ++nb) {
            const int col = bn + wn * 64 + nb * 8 + qc;
            float bx = 0.f, by = 0.f;
            if (BIAS) { bx = bias[col]; by = bias[col + 1]; }
            float c00 = acc[mt][nb][0] + bx, c01 = acc[mt][nb][1] + by;
            float c10 = acc[mt][nb][2] + bx, c11 = acc[mt][nb][3] + by;
            if (OUTH) {
                __half* C = (__half*)Cv;
                if (ok0) *(__half2*)(C + (size_t)row0 * ldC + col) = __floats2half2_rn(c00, c01);
                if (ok1) *(__half2*)(C + (size_t)row1 * ldC + col) = __floats2half2_rn(c10, c11);
            } else {
                float* C = (float*)Cv;
                if (ok0) *(float2*)(C + (size_t)row0 * ldC + col) = make_float2(c00, c01);
                if (ok1) *(float2*)(C + (size_t)row1 * ldC + col) = make_float2(c10, c11);
            }
            if (VT) {
                int sec = col / 1280;
                if (sec & 1) {                 // V or Vip section
                    int brch = sec >> 1;
                    int within = col - sec * 1280;
                    int hh = within >> 6, d = within & 63;
                    if (ok0) {
                        int bb = row0 / 77, t = row0 - bb * 77;
                        size_t base = ((((size_t)bb * 2 + brch) * NH + hh) * 64 + d) * 96 + t;
                        g_VT[base]      = __float2half(c00);
                        g_VT[base + 96] = __float2half(c01);
                    }
                    if (ok1) {
                        int bb = row1 / 77, t = row1 - bb * 77;
                        size_t base = ((((size_t)bb * 2 + brch) * NH + hh) * 64 + d) * 96 + t;
                        g_VT[base]      = __float2half(c10);
                        g_VT[base + 96] = __float2half(c11);
                    }
                }
            }
        }
    }
}

// ============================================================
// fused fp32 -> fp16 convert: hs (MQ*DD) then ehs (MKV*CDIM)
// ============================================================
__global__ void hconv2_kernel(const float* __restrict__ hs, const float* __restrict__ ehs,
                              __half* __restrict__ a, __half* __restrict__ ae)
{
    size_t i4 = ((size_t)blockIdx.x * 256 + threadIdx.x) * 4;
    const float* X;
    __half* O;
    if (i4 < (size_t)MQ * DD) { X = hs; O = a; }
    else { i4 -= (size_t)MQ * DD; X = ehs; O = ae; }
    float4 v = *(const float4*)(X + i4);
    __half2 p0 = __floats2half2_rn(v.x, v.y);
    __half2 p1 = __floats2half2_rn(v.z, v.w);
    uint2 p;
    p.x = *(uint32_t*)&p0;
    p.y = *(uint32_t*)&p1;
    *(uint2*)(O + i4) = p;
}

// ============================================================
// fused weight transpose -> fp16
// wtrans2: Wq -> g_Wth, Wo -> g_Wth2 (z selects), K=N=DD
// wtrans4: Wk/Wv/Wkip/Wvip -> g_Wkvth sections (z selects), K=CDIM, N=DD
// ============================================================
__device__ __forceinline__ void wtrans_body(const float* __restrict__ W,
                                            __half* __restrict__ out,
                                            int K, int N, int ldo, int rowoff)
{
    __shared__ float t[32][33];
    int k0 = blockIdx.x * 32, n0 = blockIdx.y * 32;
    int tx = threadIdx.x & 31, ty = threadIdx.x >> 5;
#pragma unroll
    for (int r = 0; r < 4; ++r)
        t[ty + r * 8][tx] = W[(size_t)(k0 + ty + r * 8) * N + n0 + tx];
    __syncthreads();
#pragma unroll
    for (int r = 0; r < 4; ++r) {
        int n = n0 + ty + r * 8;
        int k = k0 + tx;
        out[(size_t)(rowoff + n) * ldo + k] = __float2half(t[tx][ty + r * 8]);
    }
}

__global__ void wtrans2_kernel(const float* __restrict__ Wq, const float* __restrict__ Wo,
                               __half* __restrict__ o1, __half* __restrict__ o2)
{
    if (blockIdx.z == 0) wtrans_body(Wq, o1, DD, DD, DD, 0);
    else                 wtrans_body(Wo, o2, DD, DD, DD, 0);
}

__global__ void wtrans4_kernel(const float* __restrict__ W0, const float* __restrict__ W1,
                               const float* __restrict__ W2, const float* __restrict__ W3,
                               __half* __restrict__ out)
{
    const float* W = (blockIdx.z == 0) ? W0 : (blockIdx.z == 1) ? W1
                   : (blockIdx.z == 2) ? W2 : W3;
    wtrans_body(W, out, CDIM, DD, CDIM, blockIdx.z * 1280);
}

// ============================================================
// Boost
// ============================================================
__global__ void boost_kernel(const float* __restrict__ mask)
{
    __shared__ float red[128];
    float s = 0.f;
    for (int i = threadIdx.x; i < SS; i += 128) s += mask[i];
    red[threadIdx.x] = s;
    __syncthreads();
    for (int o = 64; o > 0; o >>= 1) {
        if (threadIdx.x < o) red[threadIdx.x] += red[threadIdx.x + o];
        __syncthreads();
    }
    if (threadIdx.x == 0) {
        float ratio = red[0] * (1.0f / (float)SS);
        float b = 1.0f;
        if (ratio > 1e-6f && ratio < 0.1f)
            b = fminf(1.0f + (0.1f - ratio) * 30.0f, 4.0f);
        g_boost = b;
    }
}

// ============================================================
// FP16 tensor-core dual-branch attention (unchanged from R14-passing).
// ============================================================
#define ATT_SQ  0          // 16384
#define ATT_SK  16384      // 10240
#define ATT_SP  26624      // 32768 (2 x 128 x 128B)
#define ATT_SV  59392      // 16384 (2 x  64 x 128B)
#define ATT_SMEM_BYTES 75776

__global__ __launch_bounds__(256, 2)
void attn_kernel(const float* __restrict__ msk)
{
    extern __shared__ char smem_raw[];
    const uint32_t sb = (uint32_t)__cvta_generic_to_shared(smem_raw);
    const int tid  = threadIdx.x;
    const int lane = tid & 31;
    const int w    = tid >> 5;
    const int b    = blockIdx.y / NH;
    const int h    = blockIdx.y % NH;
    const int s0   = blockIdx.x * 128;

    const int a_row  = (lane & 7) + ((lane & 8) ? 8 : 0);
    const int a_colb = (lane & 16) ? 16 : 0;
    const int b_row  = (lane & 7) + ((lane & 16) ? 8 : 0);
    const int b_colb = (lane & 8) ? 16 : 0;

    // pre-zero P chunk1 bytes [32,64) (t 80..95)
#pragma unroll
    for (int i = 0; i < 4; ++i) {
        int idx = tid + i * 256;
        int row = idx >> 3, c = idx & 7;
        uint32_t addr = sb + ATT_SP + 16384 + swz128((uint32_t)(row * 128 + 32 + c * 4));
        asm volatile("st.shared.f32 [%0], %1;" :: "r"(addr), "f"(0.f));
    }

    // stage Q via cp.async
    {
        const char* qh = (const char*)(g_Q + (size_t)(b * SS + s0) * DD + h * HDIM);
#pragma unroll
        for (int i = 0; i < 4; ++i) {
            int idx = tid + i * 256;
            int r = idx >> 3, seg = idx & 7;
            uint32_t d = sb + ATT_SQ + swz128((uint32_t)(r * 128 + seg * 16));
            const char* s = qh + (size_t)r * (DD * 2) + seg * 16;
            asm volatile("cp.async.cg.shared.global [%0], [%1], 16;"
                         :: "r"(d), "l"(s) : "memory");
        }
    }

    float o1[8][4];
    const float boost = g_boost;

    for (int br = 0; br < 2; ++br) {
        const char* kb = (const char*)(g_KV + (size_t)(b * SKV) * KVLD + br * 2560 + h * HDIM);
        const char* vt = (const char*)(g_VT + ((((size_t)b * 2 + br) * NH + h) * 64) * 96);

        // K: 80 rows x 8 segs (rows >= 77 zero-filled)
#pragma unroll
        for (int i = 0; i < 3; ++i) {
            int idx = tid + i * 256;
            if (idx < 640) {
                int r = idx >> 3, seg = idx & 7;
                uint32_t d = sb + ATT_SK + swz128((uint32_t)(r * 128 + seg * 16));
                const char* s = kb + (size_t)r * (KVLD * 2) + seg * 16;
                int sz = (r < SKV) ? 16 : 0;
                asm volatile("cp.async.cg.shared.global [%0], [%1], 16, %2;"
                             :: "r"(d), "l"(s), "r"(sz) : "memory");
            }
        }
        // V^T: 64 rows x 12 segs
#pragma unroll
        for (int i = 0; i < 4; ++i) {
            int idx = tid + i * 256;
            int r = idx >> 4, sg = idx & 15;
            if (sg < 12) {
                int ch = sg >> 3, s2 = sg & 7;
                uint32_t d = sb + ATT_SV + ch * 8192 + swz128((uint32_t)(r * 128 + s2 * 16));
                const char* s = vt + (size_t)r * 192 + sg * 16;
                asm volatile("cp.async.cg.shared.global [%0], [%1], 16;"
                             :: "r"(d), "l"(s) : "memory");
            }
        }
        CP_COMMIT();
        CP_WAIT0();
        __syncthreads();

        // ---- scores: S[16 x 80] per warp ----
        float sfr[10][4];
#pragma unroll
        for (int n8 = 0; n8 < 10; ++n8)
#pragma unroll
            for (int e = 0; e < 4; ++e) sfr[n8][e] = 0.f;

#pragma unroll
        for (int kk = 0; kk < 4; ++kk) {
            const int kbb = kk * 32;
            uint32_t af[4];
            LDSM_X4A(af, sb + ATT_SQ + swz128((uint32_t)((w * 16 + a_row) * 128 + kbb + a_colb)));
            uint32_t bf[5][4];
#pragma unroll
            for (int bt = 0; bt < 5; ++bt)
                LDSM_X4A(bf[bt], sb + ATT_SK
                                 + swz128((uint32_t)((bt * 16 + b_row) * 128 + kbb + b_colb)));
#pragma unroll
            for (int n8 = 0; n8 < 10; ++n8)
                MMAH(sfr[n8], af, bf[n8 >> 1][(n8 & 1) * 2], bf[n8 >> 1][(n8 & 1) * 2 + 1]);
        }

        // ---- softmax, write P~ fp16 ----
        float invs[2];
#pragma unroll
        for (int hh = 0; hh < 2; ++hh) {
            float m = -INFINITY;
#pragma unroll
            for (int n8 = 0; n8 < 10; ++n8)
#pragma unroll
                for (int j = 0; j < 2; ++j) {
                    int col = n8 * 8 + (lane & 3) * 2 + j;
                    float v = sfr[n8][hh * 2 + j] * 0.125f;
                    if (col >= SKV) v = -INFINITY;
                    sfr[n8][hh * 2 + j] = v;
                    m = fmaxf(m, v);
                }
            m = fmaxf(m, __shfl_xor_sync(0xffffffffu, m, 1));
            m = fmaxf(m, __shfl_xor_sync(0xffffffffu, m, 2));
            float s = 0.f;
#pragma unroll
            for (int n8 = 0; n8 < 10; ++n8)
#pragma unroll
                for (int j = 0; j < 2; ++j) {
                    float e = __expf(sfr[n8][hh * 2 + j] - m);
                    sfr[n8][hh * 2 + j] = e;
                    s += e;
                }
            s += __shfl_xor_sync(0xffffffffu, s, 1);
            s += __shfl_xor_sync(0xffffffffu, s, 2);
            invs[hh] = 1.0f / s;

            const int row = w * 16 + (lane >> 2) + 8 * hh;
#pragma unroll
            for (int n8 = 0; n8 < 10; ++n8) {
                int t = n8 * 8 + (lane & 3) * 2;
                __half2 hp = __floats2half2_rn(sfr[n8][hh * 2 + 0], sfr[n8][hh * 2 + 1]);
                uint32_t hv = *(uint32_t*)&hp;
                uint32_t addr = sb + ATT_SP + (t >> 6) * 16384
                              + swz128((uint32_t)(row * 128 + (t & 63) * 2));
                asm volatile("st.shared.b32 [%0], %1;" :: "r"(addr), "r"(hv));
            }
        }
        __syncthreads();

        // ---- O = P~ @ V (k = 96, deferred norm) ----
        float of[8][4];
#pragma unroll
        for (int n8 = 0; n8 < 8; ++n8)
#pragma unroll
            for (int e = 0; e < 4; ++e) of[n8][e] = 0.f;

#pragma unroll
        for (int kk = 0; kk < 6; ++kk) {
            const int ch = kk >> 2, kbb = (kk & 3) * 32;
            uint32_t af[4];
            LDSM_X4A(af, sb + ATT_SP + ch * 16384
                         + swz128((uint32_t)((w * 16 + a_row) * 128 + kbb + a_colb)));
            uint32_t bf[4][4];
#pragma unroll
            for (int bt = 0; bt < 4; ++bt)
                LDSM_X4A(bf[bt], sb + ATT_SV + ch * 8192
                                 + swz128((uint32_t)((bt * 16 + b_row) * 128 + kbb + b_colb)));
#pragma unroll
            for (int n8 = 0; n8 < 8; ++n8)
                MMAH(of[n8], af, bf[n8 >> 1][(n8 & 1) * 2], bf[n8 >> 1][(n8 & 1) * 2 + 1]);
        }

#pragma unroll
        for (int n8 = 0; n8 < 8; ++n8) {
            of[n8][0] *= invs[0]; of[n8][1] *= invs[0];
            of[n8][2] *= invs[1]; of[n8][3] *= invs[1];
        }

        if (br == 0) {
#pragma unroll
            for (int n8 = 0; n8 < 8; ++n8)
#pragma unroll
                for (int e = 0; e < 4; ++e) o1[n8][e] = of[n8][e];
            __syncthreads();
        } else {
            const int row0 = w * 16 + (lane >> 2);
            const int row1 = row0 + 8;
            const float mb0 = msk[s0 + row0] * boost;
            const float mb1 = msk[s0 + row1] * boost;
            __half* cb = g_comb + (size_t)(b * SS + s0) * DD + h * HDIM;
#pragma unroll
            for (int n8 = 0; n8 < 8; ++n8) {
                const int col = n8 * 8 + (lane & 3) * 2;
                *(__half2*)(cb + (size_t)row0 * DD + col) =
                    __floats2half2_rn(o1[n8][0] + mb0 * of[n8][0],
                                      o1[n8][1] + mb0 * of[n8][1]);
                *(__half2*)(cb + (size_t)row1 * DD + col) =
                    __floats2half2_rn(o1[n8][2] + mb1 * of[n8][2],
                                      o1[n8][3] + mb1 * of[n8][3]);
            }
        }
    }
}

// ============================================================
// launch
// ============================================================
extern "C" void kernel_launch(void* const* d_in, const int* in_sizes, int n_in,
                              void* d_out, int out_size)
{
    const float* hs   = (const float*)d_in[0];
    const float* ehs  = (const float*)d_in[1];
    const float* msk  = (const float*)d_in[2];
    const float* Wq   = (const float*)d_in[3];
    const float* Wk   = (const float*)d_in[4];
    const float* Wv   = (const float*)d_in[5];
    const float* Wkip = (const float*)d_in[6];
    const float* Wvip = (const float*)d_in[7];
    const float* Wo   = (const float*)d_in[8];
    const float* bo   = (const float*)d_in[9];
    float* out = (float*)d_out;

    __half *gAh, *gAeh, *gWth, *gWth2, *gWkvth, *gq, *gkv, *gc;
    cudaGetSymbolAddress((void**)&gAh,    g_Ah);
    cudaGetSymbolAddress((void**)&gAeh,   g_Aeh);
    cudaGetSymbolAddress((void**)&gWth,   g_Wth);
    cudaGetSymbolAddress((void**)&gWth2,  g_Wth2);
    cudaGetSymbolAddress((void**)&gWkvth, g_Wkvth);
    cudaGetSymbolAddress((void**)&gq,     g_Q);
    cudaGetSymbolAddress((void**)&gkv,    g_KV);
    cudaGetSymbolAddress((void**)&gc,     g_comb);

    cudaFuncSetAttribute((h_gemm<false, false, true,  false>),
                         cudaFuncAttributeMaxDynamicSharedMemorySize, GEMM_SMEM);
    cudaFuncSetAttribute((h_gemm<true,  false, true,  true>),
                         cudaFuncAttributeMaxDynamicSharedMemorySize, GEMM_SMEM);
    cudaFuncSetAttribute((h_gemm<false, true,  false, false>),
                         cudaFuncAttributeMaxDynamicSharedMemorySize, GEMM_SMEM);
    cudaFuncSetAttribute(attn_kernel,
                         cudaFuncAttributeMaxDynamicSharedMemorySize, ATT_SMEM_BYTES);

    // ---- fused pre-passes ----
    hconv2_kernel<<<((size_t)MQ * DD + (size_t)MKV * CDIM) / 1024, 256>>>(hs, ehs, gAh, gAeh);
    wtrans2_kernel<<<dim3(DD / 32, DD / 32, 2), 256>>>(Wq, Wo, gWth, gWth2);
    wtrans4_kernel<<<dim3(CDIM / 32, DD / 32, 4), 256>>>(Wk, Wv, Wkip, Wvip, gWkvth);
    boost_kernel<<<1, 128>>>(msk);

    // ---- Q projection (fp16 out) ----
    h_gemm<false, false, true, false><<<dim3(MQ / 128, DD / 128), 128, GEMM_SMEM>>>(
        gAh, DD, gWth, DD, DD / 64, nullptr, gq, DD, MQ);

    // ---- fused K/V/Kip/Vip projections (fp16 out + V^T scatter) ----
    h_gemm<true, false, true, true><<<dim3(3, KVLD / 128), 128, GEMM_SMEM>>>(
        gAeh, CDIM, gWkvth, CDIM, CDIM / 64, nullptr, gkv, KVLD, MKV);

    // ---- fp16 tensor-core attention (writes fp16 g_comb) ----
    attn_kernel<<<dim3(SS / 128, BB * NH), 256, ATT_SMEM_BYTES>>>(msk);

    // ---- output projection (+bias), fp32 out ----
    h_gemm<false, true, false, false><<<dim3(MQ / 128, DD / 128), 128, GEMM_SMEM>>>(
        gc, DD, gWth2, DD, DD / 64, bo, out, DD, MQ);
}

// round 17
// speedup vs baseline: 10.9213x; 1.0529x over previous
#include <cuda_runtime.h>
#include <cuda_fp16.h>
#include <math.h>
#include <stdint.h>

// ---------------- problem constants ----------------
#define BB   4
#define SS   4096
#define DD   1280
#define SKV  77
#define CDIM 2048
#define NH   20
#define HDIM 64
#define MQ   (BB*SS)    // 16384
#define MKV  (BB*SKV)   // 308
#define KVLD 5120       // fused KV row: [K|V|Kip|Vip]

// ---------------- scratch ----------------
__device__ __half g_Ah   [(size_t)MQ * DD];        // fp16(hidden_states)
__device__ __half g_Aeh  [(size_t)MKV * CDIM];     // fp16(encoder_hidden_states)
__device__ __half g_Wth  [(size_t)DD * DD];        // fp16(Wq^T)
__device__ __half g_Wth2 [(size_t)DD * DD];        // fp16(Wo^T)
__device__ __half g_Wkvth[(size_t)4 * DD * CDIM];  // fp16([Wk|Wv|Wkip|Wvip]^T)
__device__ __half g_Q    [(size_t)MQ * DD];        // fp16 Q
__device__ __half g_KV   [(size_t)MKV * KVLD];     // fp16 K/V/Kip/Vip
__device__ __half g_VT   [(size_t)BB * 2 * NH * 64 * 96]; // V^T per (b,br,h), zero-init
__device__ __half g_comb [(size_t)MQ * DD];        // fp16 attention output
__device__ float  g_boost;

// ---------------- graph fork infrastructure (static lifetime) ----------------
struct GraphStreams {
    cudaStream_t s1, s2;
    cudaEvent_t  eR, e1, e2;
    GraphStreams() {
        cudaStreamCreateWithFlags(&s1, cudaStreamNonBlocking);
        cudaStreamCreateWithFlags(&s2, cudaStreamNonBlocking);
        cudaEventCreateWithFlags(&eR, cudaEventDisableTiming);
        cudaEventCreateWithFlags(&e1, cudaEventDisableTiming);
        cudaEventCreateWithFlags(&e2, cudaEventDisableTiming);
    }
};
static GraphStreams g_gs;

// ---------------- helpers ----------------
__device__ __forceinline__ uint32_t swz128(uint32_t b) { return b ^ ((b >> 3) & 0x70); }

#define CP_COMMIT()  asm volatile("cp.async.commit_group;" ::: "memory")
#define CP_WAIT1()   asm volatile("cp.async.wait_group 1;" ::: "memory")
#define CP_WAIT0()   asm volatile("cp.async.wait_group 0;" ::: "memory")

#define LDSM_X4(r0,r1,r2,r3,addr) \
    asm volatile("ldmatrix.sync.aligned.m8n8.x4.shared.b16 {%0,%1,%2,%3}, [%4];" \
                 : "=r"(r0), "=r"(r1), "=r"(r2), "=r"(r3) : "r"(addr))
#define LDSM_X4A(r, addr) LDSM_X4((r)[0], (r)[1], (r)[2], (r)[3], addr)

// fp16 m16n8k16, fp32 accum
#define MMAH(d, a, b0, b1) \
    asm volatile("mma.sync.aligned.m16n8k16.row.col.f32.f16.f16.f32 " \
                 "{%0,%1,%2,%3}, {%4,%5,%6,%7}, {%8,%9}, {%0,%1,%2,%3};" \
                 : "+f"((d)[0]), "+f"((d)[1]), "+f"((d)[2]), "+f"((d)[3]) \
                 : "r"((a)[0]), "r"((a)[1]), "r"((a)[2]), "r"((a)[3]), \
                   "r"(b0), "r"(b1))

// ============================================================
// FP16 GEMM: CTA 128x128, 4 warps (2x2 of 64x64), K-chunk 64 fp16 (128B),
// THREE-stage cp.async pipeline, SW128 swizzle.  (identical to R15 pass)
// ============================================================
#define GSTG      32768
#define GEMM_SMEM (3 * GSTG)        // 98304

template<bool CHECK_M>
__device__ __forceinline__ void stage_chunk(uint32_t sb, int stg,
                                            const char* ab, int ldAb,
                                            const char* bb, int ldBb,
                                            int bm, int M, int tid)
{
    const uint32_t aoff = (uint32_t)stg * GSTG;
    const uint32_t boff = aoff + 16384;
#pragma unroll
    for (int i = 0; i < 8; ++i) {
        int idx = tid + i * 128;
        int r = idx >> 3, seg = idx & 7;
        uint32_t d = sb + aoff + swz128((uint32_t)(r * 128 + seg * 16));
        const char* s = ab + (size_t)r * ldAb + seg * 16;
        int sz = (!CHECK_M || (bm + r) < M) ? 16 : 0;
        asm volatile("cp.async.cg.shared.global [%0], [%1], 16, %2;"
                     :: "r"(d), "l"(s), "r"(sz) : "memory");
    }
#pragma unroll
    for (int i = 0; i < 8; ++i) {
        int idx = tid + i * 128;
        int r = idx >> 3, seg = idx & 7;
        uint32_t d = sb + boff + swz128((uint32_t)(r * 128 + seg * 16));
        const char* s = bb + (size_t)r * ldBb + seg * 16;
        asm volatile("cp.async.cg.shared.global [%0], [%1], 16;"
                     :: "r"(d), "l"(s) : "memory");
    }
}

template<bool CHECK_M, bool BIAS, bool OUTH, bool VT>
__global__ __launch_bounds__(128, 2)
void h_gemm(const __half* __restrict__ A, int ldA,
            const __half* __restrict__ Bw, int ldB, int NC,
            const float* __restrict__ bias,
            void* __restrict__ Cv, int ldC, int M)
{
    extern __shared__ char smem_raw[];
    const uint32_t sb = (uint32_t)__cvta_generic_to_shared(smem_raw);
    const int tid  = threadIdx.x;
    const int lane = tid & 31;
    const int wid  = tid >> 5;
    const int wm   = wid & 1;
    const int wn   = wid >> 1;
    const int bm   = blockIdx.x * 128;
    const int bn   = blockIdx.y * 128;

    const int ldAb = ldA * 2;
    const int ldBb = ldB * 2;
    const char* Abase = (const char*)A + (size_t)bm * ldAb;
    const char* Bbase = (const char*)Bw + (size_t)bn * ldBb;

    float acc[4][8][4];
#pragma unroll
    for (int mt = 0; mt < 4; ++mt)
#pragma unroll
        for (int nb = 0; nb < 8; ++nb)
#pragma unroll
            for (int e = 0; e < 4; ++e) acc[mt][nb][e] = 0.f;

    const int a_row  = (lane & 7) + ((lane & 8) ? 8 : 0);
    const int a_colb = (lane & 16) ? 16 : 0;
    const int b_row  = (lane & 7) + ((lane & 16) ? 8 : 0);
    const int b_colb = (lane & 8) ? 16 : 0;

    stage_chunk<CHECK_M>(sb, 0, Abase, ldAb, Bbase, ldBb, bm, M, tid);
    CP_COMMIT();
    stage_chunk<CHECK_M>(sb, 1, Abase + 128, ldAb, Bbase + 128, ldBb, bm, M, tid);
    CP_COMMIT();

    int s = 0;
    for (int c = 0; c < NC; ++c) {
        if (c + 1 < NC) CP_WAIT1(); else CP_WAIT0();
        __syncthreads();
        if (c + 2 < NC) {
            int s2 = s + 2; if (s2 >= 3) s2 -= 3;
            stage_chunk<CHECK_M>(sb, s2,
                                 Abase + (size_t)(c + 2) * 128, ldAb,
                                 Bbase + (size_t)(c + 2) * 128, ldBb, bm, M, tid);
            CP_COMMIT();
        }

        const uint32_t sA = sb + (uint32_t)s * GSTG;
        const uint32_t sB = sA + 16384;

#pragma unroll
        for (int kk = 0; kk < 4; ++kk) {
            const int kb = kk * 32;
            uint32_t afr[4][4];
#pragma unroll
            for (int mt = 0; mt < 4; ++mt)
                LDSM_X4A(afr[mt], sA + swz128((uint32_t)((wm * 64 + mt * 16 + a_row) * 128
                                                         + kb + a_colb)));
            uint32_t bfr[4][4];
#pragma unroll
            for (int nb2 = 0; nb2 < 4; ++nb2)
                LDSM_X4A(bfr[nb2], sB + swz128((uint32_t)((wn * 64 + nb2 * 16 + b_row) * 128
                                                          + kb + b_colb)));
#pragma unroll
            for (int mt = 0; mt < 4; ++mt)
#pragma unroll
                for (int nb = 0; nb < 8; ++nb)
                    MMAH(acc[mt][nb], afr[mt],
                         bfr[nb >> 1][(nb & 1) * 2], bfr[nb >> 1][(nb & 1) * 2 + 1]);
        }
        if (++s == 3) s = 0;
    }

    const int qr = lane >> 2;
    const int qc = (lane & 3) * 2;
#pragma unroll
    for (int mt = 0; mt < 4; ++mt) {
        const int row0 = bm + wm * 64 + mt * 16 + qr;
        const int row1 = row0 + 8;
        const bool ok0 = !CHECK_M || row0 < M;
        const bool ok1 = !CHECK_M || row1 < M;
#pragma unroll
        for (int nb = 0; nb < 8; ++nb) {
            const int col = bn + wn * 64 + nb * 8 + qc;
            float bx = 0.f, by = 0.f;
            if (BIAS) { bx = bias[col]; by = bias[col + 1]; }
            float c00 = acc[mt][nb][0] + bx, c01 = acc[mt][nb][1] + by;
            float c10 = acc[mt][nb][2] + bx, c11 = acc[mt][nb][3] + by;
            if (OUTH) {
                __half* C = (__half*)Cv;
                if (ok0) *(__half2*)(C + (size_t)row0 * ldC + col) = __floats2half2_rn(c00, c01);
                if (ok1) *(__half2*)(C + (size_t)row1 * ldC + col) = __floats2half2_rn(c10, c11);
            } else {
                float* C = (float*)Cv;
                if (ok0) *(float2*)(C + (size_t)row0 * ldC + col) = make_float2(c00, c01);
                if (ok1) *(float2*)(C + (size_t)row1 * ldC + col) = make_float2(c10, c11);
            }
            if (VT) {
                int sec = col / 1280;
                if (sec & 1) {
                    int brch = sec >> 1;
                    int within = col - sec * 1280;
                    int hh = within >> 6, d = within & 63;
                    if (ok0) {
                        int bb = row0 / 77, t = row0 - bb * 77;
                        size_t base = ((((size_t)bb * 2 + brch) * NH + hh) * 64 + d) * 96 + t;
                        g_VT[base]      = __float2half(c00);
                        g_VT[base + 96] = __float2half(c01);
                    }
                    if (ok1) {
                        int bb = row1 / 77, t = row1 - bb * 77;
                        size_t base = ((((size_t)bb * 2 + brch) * NH + hh) * 64 + d) * 96 + t;
                        g_VT[base]      = __float2half(c10);
                        g_VT[base + 96] = __float2half(c11);
                    }
                }
            }
        }
    }
}

// ============================================================
// fp32 -> fp16 convert (single tensor)
// ============================================================
__global__ void hconv_kernel(const float* __restrict__ X, __half* __restrict__ out)
{
    size_t i4 = ((size_t)blockIdx.x * 256 + threadIdx.x) * 4;
    float4 v = *(const float4*)(X + i4);
    __half2 p0 = __floats2half2_rn(v.x, v.y);
    __half2 p1 = __floats2half2_rn(v.z, v.w);
    uint2 p;
    p.x = *(uint32_t*)&p0;
    p.y = *(uint32_t*)&p1;
    *(uint2*)(out + i4) = p;
}

// ============================================================
// fused weight transpose -> fp16
// ============================================================
__device__ __forceinline__ void wtrans_body(const float* __restrict__ W,
                                            __half* __restrict__ out,
                                            int K, int N, int ldo, int rowoff)
{
    __shared__ float t[32][33];
    int k0 = blockIdx.x * 32, n0 = blockIdx.y * 32;
    int tx = threadIdx.x & 31, ty = threadIdx.x >> 5;
#pragma unroll
    for (int r = 0; r < 4; ++r)
        t[ty + r * 8][tx] = W[(size_t)(k0 + ty + r * 8) * N + n0 + tx];
    __syncthreads();
#pragma unroll
    for (int r = 0; r < 4; ++r) {
        int n = n0 + ty + r * 8;
        int k = k0 + tx;
        out[(size_t)(rowoff + n) * ldo + k] = __float2half(t[tx][ty + r * 8]);
    }
}

__global__ void wtrans2_kernel(const float* __restrict__ Wq, const float* __restrict__ Wo,
                               __half* __restrict__ o1, __half* __restrict__ o2)
{
    if (blockIdx.z == 0) wtrans_body(Wq, o1, DD, DD, DD, 0);
    else                 wtrans_body(Wo, o2, DD, DD, DD, 0);
}

__global__ void wtrans4_kernel(const float* __restrict__ W0, const float* __restrict__ W1,
                               const float* __restrict__ W2, const float* __restrict__ W3,
                               __half* __restrict__ out)
{
    const float* W = (blockIdx.z == 0) ? W0 : (blockIdx.z == 1) ? W1
                   : (blockIdx.z == 2) ? W2 : W3;
    wtrans_body(W, out, CDIM, DD, CDIM, blockIdx.z * 1280);
}

// ============================================================
// Boost
// ============================================================
__global__ void boost_kernel(const float* __restrict__ mask)
{
    __shared__ float red[128];
    float s = 0.f;
    for (int i = threadIdx.x; i < SS; i += 128) s += mask[i];
    red[threadIdx.x] = s;
    __syncthreads();
    for (int o = 64; o > 0; o >>= 1) {
        if (threadIdx.x < o) red[threadIdx.x] += red[threadIdx.x + o];
        __syncthreads();
    }
    if (threadIdx.x == 0) {
        float ratio = red[0] * (1.0f / (float)SS);
        float b = 1.0f;
        if (ratio > 1e-6f && ratio < 0.1f)
            b = fminf(1.0f + (0.1f - ratio) * 30.0f, 4.0f);
        g_boost = b;
    }
}

// ============================================================
// FP16 tensor-core dual-branch attention (identical to R15 pass)
// ============================================================
#define ATT_SQ  0
#define ATT_SK  16384
#define ATT_SP  26624
#define ATT_SV  59392
#define ATT_SMEM_BYTES 75776

__global__ __launch_bounds__(256, 2)
void attn_kernel(const float* __restrict__ msk)
{
    extern __shared__ char smem_raw[];
    const uint32_t sb = (uint32_t)__cvta_generic_to_shared(smem_raw);
    const int tid  = threadIdx.x;
    const int lane = tid & 31;
    const int w    = tid >> 5;
    const int b    = blockIdx.y / NH;
    const int h    = blockIdx.y % NH;
    const int s0   = blockIdx.x * 128;

    const int a_row  = (lane & 7) + ((lane & 8) ? 8 : 0);
    const int a_colb = (lane & 16) ? 16 : 0;
    const int b_row  = (lane & 7) + ((lane & 16) ? 8 : 0);
    const int b_colb = (lane & 8) ? 16 : 0;

#pragma unroll
    for (int i = 0; i < 4; ++i) {
        int idx = tid + i * 256;
        int row = idx >> 3, c = idx & 7;
        uint32_t addr = sb + ATT_SP + 16384 + swz128((uint32_t)(row * 128 + 32 + c * 4));
        asm volatile("st.shared.f32 [%0], %1;" :: "r"(addr), "f"(0.f));
    }

    {
        const char* qh = (const char*)(g_Q + (size_t)(b * SS + s0) * DD + h * HDIM);
#pragma unroll
        for (int i = 0; i < 4; ++i) {
            int idx = tid + i * 256;
            int r = idx >> 3, seg = idx & 7;
            uint32_t d = sb + ATT_SQ + swz128((uint32_t)(r * 128 + seg * 16));
            const char* s = qh + (size_t)r * (DD * 2) + seg * 16;
            asm volatile("cp.async.cg.shared.global [%0], [%1], 16;"
                         :: "r"(d), "l"(s) : "memory");
        }
    }

    float o1[8][4];
    const float boost = g_boost;

    for (int br = 0; br < 2; ++br) {
        const char* kb = (const char*)(g_KV + (size_t)(b * SKV) * KVLD + br * 2560 + h * HDIM);
        const char* vt = (const char*)(g_VT + ((((size_t)b * 2 + br) * NH + h) * 64) * 96);

#pragma unroll
        for (int i = 0; i < 3; ++i) {
            int idx = tid + i * 256;
            if (idx < 640) {
                int r = idx >> 3, seg = idx & 7;
                uint32_t d = sb + ATT_SK + swz128((uint32_t)(r * 128 + seg * 16));
                const char* s = kb + (size_t)r * (KVLD * 2) + seg * 16;
                int sz = (r < SKV) ? 16 : 0;
                asm volatile("cp.async.cg.shared.global [%0], [%1], 16, %2;"
                             :: "r"(d), "l"(s), "r"(sz) : "memory");
            }
        }
#pragma unroll
        for (int i = 0; i < 4; ++i) {
            int idx = tid + i * 256;
            int r = idx >> 4, sg = idx & 15;
            if (sg < 12) {
                int ch = sg >> 3, s2 = sg & 7;
                uint32_t d = sb + ATT_SV + ch * 8192 + swz128((uint32_t)(r * 128 + s2 * 16));
                const char* s = vt + (size_t)r * 192 + sg * 16;
                asm volatile("cp.async.cg.shared.global [%0], [%1], 16;"
                             :: "r"(d), "l"(s) : "memory");
            }
        }
        CP_COMMIT();
        CP_WAIT0();
        __syncthreads();

        float sfr[10][4];
#pragma unroll
        for (int n8 = 0; n8 < 10; ++n8)
#pragma unroll
            for (int e = 0; e < 4; ++e) sfr[n8][e] = 0.f;

#pragma unroll
        for (int kk = 0; kk < 4; ++kk) {
            const int kbb = kk * 32;
            uint32_t af[4];
            LDSM_X4A(af, sb + ATT_SQ + swz128((uint32_t)((w * 16 + a_row) * 128 + kbb + a_colb)));
            uint32_t bf[5][4];
#pragma unroll
            for (int bt = 0; bt < 5; ++bt)
                LDSM_X4A(bf[bt], sb + ATT_SK
                                 + swz128((uint32_t)((bt * 16 + b_row) * 128 + kbb + b_colb)));
#pragma unroll
            for (int n8 = 0; n8 < 10; ++n8)
                MMAH(sfr[n8], af, bf[n8 >> 1][(n8 & 1) * 2], bf[n8 >> 1][(n8 & 1) * 2 + 1]);
        }

        float invs[2];
#pragma unroll
        for (int hh = 0; hh < 2; ++hh) {
            float m = -INFINITY;
#pragma unroll
            for (int n8 = 0; n8 < 10; ++n8)
#pragma unroll
                for (int j = 0; j < 2; ++j) {
                    int col = n8 * 8 + (lane & 3) * 2 + j;
                    float v = sfr[n8][hh * 2 + j] * 0.125f;
                    if (col >= SKV) v = -INFINITY;
                    sfr[n8][hh * 2 + j] = v;
                    m = fmaxf(m, v);
                }
            m = fmaxf(m, __shfl_xor_sync(0xffffffffu, m, 1));
            m = fmaxf(m, __shfl_xor_sync(0xffffffffu, m, 2));
            float s = 0.f;
#pragma unroll
            for (int n8 = 0; n8 < 10; ++n8)
#pragma unroll
                for (int j = 0; j < 2; ++j) {
                    float e = __expf(sfr[n8][hh * 2 + j] - m);
                    sfr[n8][hh * 2 + j] = e;
                    s += e;
                }
            s += __shfl_xor_sync(0xffffffffu, s, 1);
            s += __shfl_xor_sync(0xffffffffu, s, 2);
            invs[hh] = 1.0f / s;

            const int row = w * 16 + (lane >> 2) + 8 * hh;
#pragma unroll
            for (int n8 = 0; n8 < 10; ++n8) {
                int t = n8 * 8 + (lane & 3) * 2;
                __half2 hp = __floats2half2_rn(sfr[n8][hh * 2 + 0], sfr[n8][hh * 2 + 1]);
                uint32_t hv = *(uint32_t*)&hp;
                uint32_t addr = sb + ATT_SP + (t >> 6) * 16384
                              + swz128((uint32_t)(row * 128 + (t & 63) * 2));
                asm volatile("st.shared.b32 [%0], %1;" :: "r"(addr), "r"(hv));
            }
        }
        __syncthreads();

        float of[8][4];
#pragma unroll
        for (int n8 = 0; n8 < 8; ++n8)
#pragma unroll
            for (int e = 0; e < 4; ++e) of[n8][e] = 0.f;

#pragma unroll
        for (int kk = 0; kk < 6; ++kk) {
            const int ch = kk >> 2, kbb = (kk & 3) * 32;
            uint32_t af[4];
            LDSM_X4A(af, sb + ATT_SP + ch * 16384
                         + swz128((uint32_t)((w * 16 + a_row) * 128 + kbb + a_colb)));
            uint32_t bf[4][4];
#pragma unroll
            for (int bt = 0; bt < 4; ++bt)
                LDSM_X4A(bf[bt], sb + ATT_SV + ch * 8192
                                 + swz128((uint32_t)((bt * 16 + b_row) * 128 + kbb + b_colb)));
#pragma unroll
            for (int n8 = 0; n8 < 8; ++n8)
                MMAH(of[n8], af, bf[n8 >> 1][(n8 & 1) * 2], bf[n8 >> 1][(n8 & 1) * 2 + 1]);
        }

#pragma unroll
        for (int n8 = 0; n8 < 8; ++n8) {
            of[n8][0] *= invs[0]; of[n8][1] *= invs[0];
            of[n8][2] *= invs[1]; of[n8][3] *= invs[1];
        }

        if (br == 0) {
#pragma unroll
            for (int n8 = 0; n8 < 8; ++n8)
#pragma unroll
                for (int e = 0; e < 4; ++e) o1[n8][e] = of[n8][e];
            __syncthreads();
        } else {
            const int row0 = w * 16 + (lane >> 2);
            const int row1 = row0 + 8;
            const float mb0 = msk[s0 + row0] * boost;
            const float mb1 = msk[s0 + row1] * boost;
            __half* cb = g_comb + (size_t)(b * SS + s0) * DD + h * HDIM;
#pragma unroll
            for (int n8 = 0; n8 < 8; ++n8) {
                const int col = n8 * 8 + (lane & 3) * 2;
                *(__half2*)(cb + (size_t)row0 * DD + col) =
                    __floats2half2_rn(o1[n8][0] + mb0 * of[n8][0],
                                      o1[n8][1] + mb0 * of[n8][1]);
                *(__half2*)(cb + (size_t)row1 * DD + col) =
                    __floats2half2_rn(o1[n8][2] + mb1 * of[n8][2],
                                      o1[n8][3] + mb1 * of[n8][3]);
            }
        }
    }
}

// ============================================================
// launch — forked graph:
//   s1: hconv(ehs) -> wtrans4 -> KV-GEMM -> boost -> e1
//   s2: wtrans2(Wq,Wo) -> e2
//   0 : hconv(hs) -> [e2] Q-GEMM -> [e1] attn -> out-GEMM
// ============================================================
extern "C" void kernel_launch(void* const* d_in, const int* in_sizes, int n_in,
                              void* d_out, int out_size)
{
    const float* hs   = (const float*)d_in[0];
    const float* ehs  = (const float*)d_in[1];
    const float* msk  = (const float*)d_in[2];
    const float* Wq   = (const float*)d_in[3];
    const float* Wk   = (const float*)d_in[4];
    const float* Wv   = (const float*)d_in[5];
    const float* Wkip = (const float*)d_in[6];
    const float* Wvip = (const float*)d_in[7];
    const float* Wo   = (const float*)d_in[8];
    const float* bo   = (const float*)d_in[9];
    float* out = (float*)d_out;

    __half *gAh, *gAeh, *gWth, *gWth2, *gWkvth, *gq, *gkv, *gc;
    cudaGetSymbolAddress((void**)&gAh,    g_Ah);
    cudaGetSymbolAddress((void**)&gAeh,   g_Aeh);
    cudaGetSymbolAddress((void**)&gWth,   g_Wth);
    cudaGetSymbolAddress((void**)&gWth2,  g_Wth2);
    cudaGetSymbolAddress((void**)&gWkvth, g_Wkvth);
    cudaGetSymbolAddress((void**)&gq,     g_Q);
    cudaGetSymbolAddress((void**)&gkv,    g_KV);
    cudaGetSymbolAddress((void**)&gc,     g_comb);

    cudaFuncSetAttribute((h_gemm<false, false, true,  false>),
                         cudaFuncAttributeMaxDynamicSharedMemorySize, GEMM_SMEM);
    cudaFuncSetAttribute((h_gemm<true,  false, true,  true>),
                         cudaFuncAttributeMaxDynamicSharedMemorySize, GEMM_SMEM);
    cudaFuncSetAttribute((h_gemm<false, true,  false, false>),
                         cudaFuncAttributeMaxDynamicSharedMemorySize, GEMM_SMEM);
    cudaFuncSetAttribute(attn_kernel,
                         cudaFuncAttributeMaxDynamicSharedMemorySize, ATT_SMEM_BYTES);

    // ---- fork ----
    cudaEventRecord(g_gs.eR, 0);
    cudaStreamWaitEvent(g_gs.s1, g_gs.eR, 0);
    cudaStreamWaitEvent(g_gs.s2, g_gs.eR, 0);

    // branch s1: encoder side (KV) + boost
    hconv_kernel<<<(MKV * CDIM) / 1024, 256, 0, g_gs.s1>>>(ehs, gAeh);
    wtrans4_kernel<<<dim3(CDIM / 32, DD / 32, 4), 256, 0, g_gs.s1>>>(Wk, Wv, Wkip, Wvip, gWkvth);
    h_gemm<true, false, true, true><<<dim3(3, KVLD / 128), 128, GEMM_SMEM, g_gs.s1>>>(
        gAeh, CDIM, gWkvth, CDIM, CDIM / 64, nullptr, gkv, KVLD, MKV);
    boost_kernel<<<1, 128, 0, g_gs.s1>>>(msk);
    cudaEventRecord(g_gs.e1, g_gs.s1);

    // branch s2: Wq/Wo transpose
    wtrans2_kernel<<<dim3(DD / 32, DD / 32, 2), 256, 0, g_gs.s2>>>(Wq, Wo, gWth, gWth2);
    cudaEventRecord(g_gs.e2, g_gs.s2);

    // main: hs convert -> Q-GEMM -> attn -> out-GEMM
    hconv_kernel<<<(MQ * DD) / 1024, 256>>>(hs, gAh);
    cudaStreamWaitEvent(0, g_gs.e2, 0);
    h_gemm<false, false, true, false><<<dim3(MQ / 128, DD / 128), 128, GEMM_SMEM>>>(
        gAh, DD, gWth, DD, DD / 64, nullptr, gq, DD, MQ);
    cudaStreamWaitEvent(0, g_gs.e1, 0);
    attn_kernel<<<dim3(SS / 128, BB * NH), 256, ATT_SMEM_BYTES>>>(msk);
    h_gemm<false, true, false, false><<<dim3(MQ / 128, DD / 128), 128, GEMM_SMEM>>>(
        gc, DD, gWth2, DD, DD / 64, bo, out, DD, MQ);
}